// round 3
// baseline (speedup 1.0000x reference)
#include <cuda_runtime.h>
#include <cuda_bf16.h>

// Problem dims (fixed)
#define BATCH   4
#define LENGTH  2048
#define DMODEL  1024
#define DINNER  2048
#define DSTATE  16
#define DTRANK  64
#define DCONV   4
#define BL      (BATCH*LENGTH)        // 8192 rows
#define D2      (2*DINNER)            // 4096
#define DBCW    (DTRANK + 2*DSTATE)   // 96

// -------- scratch (static device allocations; no cudaMalloc allowed) --------
__device__ float g_xz[(size_t)BL * D2];        // 134 MB : [xc | z]
__device__ float g_xc[(size_t)BL * DINNER];    //  67 MB : conv+silu output
__device__ float g_dbc[(size_t)BL * DBCW];     //   3 MB : [dt(64) | B(16) | C(16)]
__device__ float g_delta[(size_t)BL * DINNER]; //  67 MB
__device__ float g_y[(size_t)BL * DINNER];     //  67 MB : gated scan output

// ---------------------------------------------------------------------------
// Generic fp32 "NT" GEMM:  C[m][n] = sum_k A[m*lda+k] * B[n*ldb+k]
// Both operands K-contiguous (row-major with K inner) which matches every
// einsum in this problem. 128x128 block tile, BK=8, 256 threads, 8x8 micro.
// EPI: 0 = plain store, 1 = softplus(v + bias[n])
// ---------------------------------------------------------------------------
template<int EPI>
__global__ __launch_bounds__(256)
void sgemm_nt(const float* __restrict__ A, int lda,
              const float* __restrict__ B, int ldb,
              float* __restrict__ C, int ldc,
              int N, int K,
              const float* __restrict__ bias)
{
    const int BM = 128, BN = 128, BK = 8;
    __shared__ float As[BK][BM];
    __shared__ float Bs[BK][BN + 4];

    const int bm  = blockIdx.y * BM;
    const int bn  = blockIdx.x * BN;
    const int tid = threadIdx.x;

    // load mapping: 256 threads, each one float4 of A and one of B per tile
    const int lrow = tid >> 1;            // 0..127
    const int lk4  = (tid & 1) * 4;       // 0 or 4

    const float* Aptr = A + (size_t)(bm + lrow) * lda + lk4;
    const bool   bval = (bn + lrow) < N;
    const float* Bptr = B + (size_t)(bn + lrow) * ldb + lk4;

    const int tx = tid & 15;              // col group
    const int ty = tid >> 4;              // row group
    const int r0 = ty * 8;
    const int c0 = tx * 8;

    float acc[8][8];
#pragma unroll
    for (int i = 0; i < 8; i++)
#pragma unroll
        for (int j = 0; j < 8; j++) acc[i][j] = 0.f;

    const int ntiles = K / BK;
    float4 av = *(const float4*)Aptr;
    float4 bv = bval ? *(const float4*)Bptr : make_float4(0.f,0.f,0.f,0.f);

    for (int t = 0; t < ntiles; ++t) {
        __syncthreads();
        As[lk4 + 0][lrow] = av.x;
        As[lk4 + 1][lrow] = av.y;
        As[lk4 + 2][lrow] = av.z;
        As[lk4 + 3][lrow] = av.w;
        Bs[lk4 + 0][lrow] = bv.x;
        Bs[lk4 + 1][lrow] = bv.y;
        Bs[lk4 + 2][lrow] = bv.z;
        Bs[lk4 + 3][lrow] = bv.w;
        __syncthreads();

        if (t + 1 < ntiles) {  // prefetch next tile (overlaps compute)
            Aptr += BK; Bptr += BK;
            av = *(const float4*)Aptr;
            bv = bval ? *(const float4*)Bptr : make_float4(0.f,0.f,0.f,0.f);
        }

#pragma unroll
        for (int k = 0; k < BK; ++k) {
            float4 a0 = *(const float4*)&As[k][r0];
            float4 a1 = *(const float4*)&As[k][r0 + 4];
            float4 b0 = *(const float4*)&Bs[k][c0];
            float4 b1 = *(const float4*)&Bs[k][c0 + 4];
            float ar[8] = {a0.x,a0.y,a0.z,a0.w,a1.x,a1.y,a1.z,a1.w};
            float br[8] = {b0.x,b0.y,b0.z,b0.w,b1.x,b1.y,b1.z,b1.w};
#pragma unroll
            for (int i = 0; i < 8; i++)
#pragma unroll
                for (int j = 0; j < 8; j++)
                    acc[i][j] = fmaf(ar[i], br[j], acc[i][j]);
        }
    }

    // epilogue
#pragma unroll
    for (int i = 0; i < 8; i++) {
        const size_t row = (size_t)(bm + r0 + i) * ldc;
#pragma unroll
        for (int j = 0; j < 8; j++) {
            const int col = bn + c0 + j;
            if (col < N) {
                float v = acc[i][j];
                if (EPI == 1) {
                    v += bias[col];
                    v = (v > 20.f) ? v : log1pf(__expf(v));
                }
                C[row + col] = v;
            }
        }
    }
}

// ---------------------------------------------------------------------------
// Causal depthwise conv (k=4) + bias + SiLU over the xc half of g_xz
// ---------------------------------------------------------------------------
__global__ __launch_bounds__(256)
void conv_silu_kernel(const float* __restrict__ conv_w,
                      const float* __restrict__ conv_b)
{
    const size_t idx = (size_t)blockIdx.x * blockDim.x + threadIdx.x;
    if (idx >= (size_t)BL * DINNER) return;
    const int d  = (int)(idx % DINNER);
    const size_t bl = idx / DINNER;
    const int l  = (int)(bl % LENGTH);
    const size_t brow = (bl - l) * (size_t)D2;  // start of this batch's rows in xz

    float acc = conv_b[d];
    const float w0 = conv_w[d*4+0], w1 = conv_w[d*4+1];
    const float w2 = conv_w[d*4+2], w3 = conv_w[d*4+3];
    const float* base = g_xz + brow + d;
    if (l >= 3)      acc += w0 * base[(size_t)(l-3)*D2];
    if (l >= 2)      acc += w1 * base[(size_t)(l-2)*D2];
    if (l >= 1)      acc += w2 * base[(size_t)(l-1)*D2];
    acc += w3 * base[(size_t)l*D2];

    g_xc[idx] = acc / (1.f + __expf(-acc));   // silu
}

// ---------------------------------------------------------------------------
// Selective scan. 4 threads per (b,d) channel, 4 states each (16 total),
// shuffle-reduce the C·h dot, fused with D*x skip and silu(z) gating.
// grid = BATCH*64 blocks of 128 threads (32 channels / block).
// ---------------------------------------------------------------------------
__global__ __launch_bounds__(128)
void scan_kernel(const float* __restrict__ A_raw,
                 const float* __restrict__ Dvec)
{
    const int tid = threadIdx.x;
    const int sub = tid & 3;          // which 4-state group
    const int cl  = tid >> 2;         // channel within block
    const int blk = blockIdx.x;
    const int b   = blk >> 6;
    const int c   = ((blk & 63) << 5) + cl;

    const float a0 = -__expf(A_raw[(sub*4+0)*DINNER + c]);
    const float a1 = -__expf(A_raw[(sub*4+1)*DINNER + c]);
    const float a2 = -__expf(A_raw[(sub*4+2)*DINNER + c]);
    const float a3 = -__expf(A_raw[(sub*4+3)*DINNER + c]);
    const float Dv = Dvec[c];

    float h0=0.f, h1=0.f, h2=0.f, h3=0.f;

    const float* dptr  = g_delta + (size_t)b*LENGTH*DINNER + c;
    const float* xptr  = g_xc    + (size_t)b*LENGTH*DINNER + c;
    const float* bcptr = g_dbc   + (size_t)b*LENGTH*DBCW + DTRANK + sub*4;
    const float* zptr  = g_xz    + (size_t)b*LENGTH*D2 + DINNER + c;
    float*       yptr  = g_y     + (size_t)b*LENGTH*DINNER + c;

    for (int t = 0; t < LENGTH; ++t) {
        const float delta = *dptr;
        const float x     = *xptr;
        const float4 Bv = *(const float4*)(bcptr);
        const float4 Cv = *(const float4*)(bcptr + DSTATE);
        const float dx  = delta * x;

        h0 = fmaf(__expf(delta * a0), h0, Bv.x * dx);
        h1 = fmaf(__expf(delta * a1), h1, Bv.y * dx);
        h2 = fmaf(__expf(delta * a2), h2, Bv.z * dx);
        h3 = fmaf(__expf(delta * a3), h3, Bv.w * dx);

        float acc = Cv.x*h0 + Cv.y*h1 + Cv.z*h2 + Cv.w*h3;
        acc += __shfl_xor_sync(0xffffffffu, acc, 1);
        acc += __shfl_xor_sync(0xffffffffu, acc, 2);

        if (sub == 0) {
            const float z = *zptr;
            *yptr = (acc + Dv * x) * (z / (1.f + __expf(-z)));
        }

        dptr += DINNER; xptr += DINNER; bcptr += DBCW;
        zptr += D2;     yptr += DINNER;
    }
}

// ---------------------------------------------------------------------------
extern "C" void kernel_launch(void* const* d_in, const int* in_sizes, int n_in,
                              void* d_out, int out_size)
{
    const float* x      = (const float*)d_in[0];  // (4,2048,1024)
    const float* W_in   = (const float*)d_in[1];  // (4096,1024)
    const float* conv_w = (const float*)d_in[2];  // (2048,1,4)
    const float* conv_b = (const float*)d_in[3];  // (2048,)
    const float* W_x    = (const float*)d_in[4];  // (96,2048)
    const float* W_dt   = (const float*)d_in[5];  // (2048,64)
    const float* b_dt   = (const float*)d_in[6];  // (2048,)
    const float* A_raw  = (const float*)d_in[7];  // (16,2048)
    const float* Dvec   = (const float*)d_in[8];  // (2048,)
    const float* W_out  = (const float*)d_in[9];  // (1024,2048)
    float* out = (float*)d_out;                   // (4,2048,1024)

    float *p_xz, *p_xc, *p_dbc, *p_delta, *p_y;
    cudaGetSymbolAddress((void**)&p_xz,    g_xz);
    cudaGetSymbolAddress((void**)&p_xc,    g_xc);
    cudaGetSymbolAddress((void**)&p_dbc,   g_dbc);
    cudaGetSymbolAddress((void**)&p_delta, g_delta);
    cudaGetSymbolAddress((void**)&p_y,     g_y);

    // 1) xz = x @ W_in^T      (8192 x 4096, K=1024)
    sgemm_nt<0><<<dim3(D2/128, BL/128), 256>>>(
        x, DMODEL, W_in, DMODEL, p_xz, D2, D2, DMODEL, nullptr);

    // 2) causal depthwise conv + silu on xc half
    {
        const size_t total = (size_t)BL * DINNER;
        conv_silu_kernel<<<(unsigned)((total + 255) / 256), 256>>>(conv_w, conv_b);
    }

    // 3) dbc = xc @ W_x^T     (8192 x 96, K=2048)
    sgemm_nt<0><<<dim3(1, BL/128), 256>>>(
        p_xc, DINNER, W_x, DINNER, p_dbc, DBCW, DBCW, DINNER, nullptr);

    // 4) delta = softplus(dt @ W_dt^T + b_dt)   (8192 x 2048, K=64, lda=96)
    sgemm_nt<1><<<dim3(DINNER/128, BL/128), 256>>>(
        p_dbc, DBCW, W_dt, DTRANK, p_delta, DINNER, DINNER, DTRANK, b_dt);

    // 5) selective scan + D*x skip + silu(z) gate  -> g_y
    scan_kernel<<<BATCH * 64, 128>>>(A_raw, Dvec);

    // 6) out = y @ W_out^T    (8192 x 1024, K=2048)
    sgemm_nt<0><<<dim3(DMODEL/128, BL/128), 256>>>(
        p_y, DINNER, W_out, DINNER, out, DMODEL, DMODEL, DINNER, nullptr);
}

// round 5
// speedup vs baseline: 1.5539x; 1.5539x over previous
#include <cuda_runtime.h>
#include <cuda_bf16.h>
#include <cstdint>

// Problem dims (fixed)
#define BATCH   4
#define LENGTH  2048
#define DMODEL  1024
#define DINNER  2048
#define DSTATE  16
#define DTRANK  64
#define BL      (BATCH*LENGTH)        // 8192
#define D2      (2*DINNER)            // 4096
#define DBCW    (DTRANK + 2*DSTATE)   // 96

// ------------------- static scratch (no cudaMalloc allowed) -------------------
__device__ float g_xz[(size_t)BL * D2];
__device__ float g_xc[(size_t)BL * DINNER];
__device__ float g_dbc[(size_t)BL * DBCW];
__device__ float g_delta[(size_t)BL * DINNER];

__device__ __nv_bfloat16 g_xh  [(size_t)BL*DMODEL],   g_xl  [(size_t)BL*DMODEL];
__device__ __nv_bfloat16 g_winh[(size_t)D2*DMODEL],   g_winl[(size_t)D2*DMODEL];
__device__ __nv_bfloat16 g_xch [(size_t)BL*DINNER],   g_xcl [(size_t)BL*DINNER];
__device__ __nv_bfloat16 g_wxh [(size_t)DBCW*DINNER], g_wxl [(size_t)DBCW*DINNER];
__device__ __nv_bfloat16 g_dth [(size_t)BL*DTRANK],   g_dtl [(size_t)BL*DTRANK];
__device__ __nv_bfloat16 g_wdth[(size_t)DINNER*DTRANK],g_wdtl[(size_t)DINNER*DTRANK];
__device__ __nv_bfloat16 g_yh  [(size_t)BL*DINNER],   g_yl  [(size_t)BL*DINNER];
__device__ __nv_bfloat16 g_wouth[(size_t)DMODEL*DINNER],g_woutl[(size_t)DMODEL*DINNER];

// ------------------------------ PTX helpers ------------------------------
__device__ __forceinline__ uint32_t s2u(const void* p) {
    uint32_t a;
    asm("{ .reg .u64 t; cvta.to.shared.u64 t, %1; cvt.u32.u64 %0, t; }" : "=r"(a) : "l"(p));
    return a;
}
#define CP16(d, g) \
    asm volatile("cp.async.cg.shared.global [%0], [%1], 16;" :: "r"(d), "l"(g))
#define CP16Z(d, g, v) \
    asm volatile("cp.async.cg.shared.global [%0], [%1], 16, %2;" :: "r"(d), "l"(g), "r"(v))
#define CP_COMMIT() asm volatile("cp.async.commit_group;" ::: "memory")
#define CP_WAIT0()  asm volatile("cp.async.wait_group 0;" ::: "memory")

#define LDSM4(r, a) \
    asm volatile("ldmatrix.sync.aligned.m8n8.x4.shared.b16 {%0,%1,%2,%3}, [%4];" \
        : "=r"((r)[0]), "=r"((r)[1]), "=r"((r)[2]), "=r"((r)[3]) : "r"(a))

#define MMA16816(c, a, b0, b1) \
    asm volatile("mma.sync.aligned.m16n8k16.row.col.f32.bf16.bf16.f32 " \
        "{%0,%1,%2,%3}, {%4,%5,%6,%7}, {%8,%9}, {%0,%1,%2,%3};" \
        : "+f"((c)[0]), "+f"((c)[1]), "+f"((c)[2]), "+f"((c)[3]) \
        : "r"((a)[0]), "r"((a)[1]), "r"((a)[2]), "r"((a)[3]), "r"(b0), "r"(b1))

// ---------------------------------------------------------------------------
// Split-bf16 3-pass warp-MMA GEMM: C[m][n] = sum_k A[m][k]*B[n][k] (fp32 out)
// CTA tile 128x128, BK=32, 256 threads (2x4 warps, warp tile 64x32).
// Smem rows padded to 80B -> conflict-free ldmatrix; cp.async double buffer.
// EPI: 0 = plain store, 1 = softplus(v + bias[n]).
// GUARD: bounds-check B rows / C cols against Nt (for the N=96 GEMM).
// ---------------------------------------------------------------------------
#define STG_A_L 10240u          // offset of A_lo within stage
#define STG_B_H 20480u          // offset of B_hi
#define STG_B_L 30720u
#define STG_SZ  40960u          // bytes per stage (4 matrices, 128 rows * 80B)

template<int EPI, bool GUARD>
__global__ __launch_bounds__(256, 1)
void tgemm(const __nv_bfloat16* __restrict__ Ah, const __nv_bfloat16* __restrict__ Al, int lda,
           const __nv_bfloat16* __restrict__ Bh, const __nv_bfloat16* __restrict__ Bl, int ldb,
           float* __restrict__ C, int ldc, int Nt, int K,
           const float* __restrict__ bias)
{
    extern __shared__ char smem[];
    const uint32_t sb = s2u(smem);

    const int tid = threadIdx.x;
    const int lid = tid & 31;
    const int wid = tid >> 5;
    const int wm0 = (wid & 1) * 64;    // warp m offset in CTA tile
    const int wn0 = (wid >> 1) * 32;   // warp n offset

    const int bm = blockIdx.y * 128;
    const int bn = blockIdx.x * 128;

    float acc[4][4][4];
#pragma unroll
    for (int i = 0; i < 4; i++)
#pragma unroll
        for (int j = 0; j < 4; j++)
#pragma unroll
            for (int k = 0; k < 4; k++) acc[i][j][k] = 0.f;

    // stage loader: 4 matrices x 512 16B-chunks, 2 chunks/thread/matrix
    auto ld_stage = [&](int s, int kc) {
        const uint32_t base = sb + (uint32_t)s * STG_SZ;
        const __nv_bfloat16* pAh = Ah + (size_t)bm * lda + kc;
        const __nv_bfloat16* pAl = Al + (size_t)bm * lda + kc;
        const __nv_bfloat16* pBh = Bh + (size_t)bn * ldb + kc;
        const __nv_bfloat16* pBl = Bl + (size_t)bn * ldb + kc;
#pragma unroll
        for (int i = 0; i < 2; i++) {
            const int c   = tid + i * 256;
            const int row = c >> 2;
            const int ch  = (c & 3) * 16;
            const uint32_t o = (uint32_t)row * 80u + (uint32_t)ch;
            CP16(base + o,           (const char*)(pAh + (size_t)row * lda) + ch);
            CP16(base + STG_A_L + o, (const char*)(pAl + (size_t)row * lda) + ch);
            if (!GUARD) {
                CP16(base + STG_B_H + o, (const char*)(pBh + (size_t)row * ldb) + ch);
                CP16(base + STG_B_L + o, (const char*)(pBl + (size_t)row * ldb) + ch);
            } else {
                const uint32_t v = ((bn + row) < Nt) ? 16u : 0u;
                CP16Z(base + STG_B_H + o, (const char*)(pBh + (size_t)row * ldb) + ch, v);
                CP16Z(base + STG_B_L + o, (const char*)(pBl + (size_t)row * ldb) + ch, v);
            }
        }
    };

    // per-lane ldmatrix addressing
    const uint32_t arow  = (uint32_t)(wm0 + (lid & 15));
    const uint32_t akoff = (uint32_t)((lid >> 4) << 3);
    const uint32_t brow  = (uint32_t)(wn0 + ((lid >> 4) << 3) + (lid & 7));
    const uint32_t bkoff = (uint32_t)(((lid >> 3) & 1) << 3);

    auto compute = [&](int s) {
        const uint32_t aB = sb + (uint32_t)s * STG_SZ;
        const uint32_t bB = aB + STG_B_H;
#pragma unroll
        for (int kk = 0; kk < 2; ++kk) {
            uint32_t ah[4][4], al[4][4];
#pragma unroll
            for (int mi = 0; mi < 4; mi++) {
                const uint32_t ad = aB + (arow + mi*16) * 80u + (akoff + kk*16) * 2u;
                LDSM4(ah[mi], ad);
                LDSM4(al[mi], ad + STG_A_L);
            }
            uint32_t bh[2][4], bl[2][4];
#pragma unroll
            for (int bi = 0; bi < 2; bi++) {
                const uint32_t bd = bB + (brow + bi*16) * 80u + (bkoff + kk*16) * 2u;
                LDSM4(bh[bi], bd);
                LDSM4(bl[bi], bd + STG_A_L);  // B_lo is +10240 from B_hi
            }
#pragma unroll
            for (int mi = 0; mi < 4; mi++)
#pragma unroll
                for (int nt = 0; nt < 4; nt++) {
                    const uint32_t b0h = bh[nt>>1][(nt&1)*2], b1h = bh[nt>>1][(nt&1)*2+1];
                    const uint32_t b0l = bl[nt>>1][(nt&1)*2], b1l = bl[nt>>1][(nt&1)*2+1];
                    MMA16816(acc[mi][nt], ah[mi], b0h, b1h);
                    MMA16816(acc[mi][nt], ah[mi], b0l, b1l);
                    MMA16816(acc[mi][nt], al[mi], b0h, b1h);
                }
        }
    };

    const int nit = K >> 5;
    ld_stage(0, 0);
    CP_COMMIT();
    for (int it = 0; it < nit; ++it) {
        CP_WAIT0();
        __syncthreads();
        if (it + 1 < nit) { ld_stage((it + 1) & 1, (it + 1) * 32); CP_COMMIT(); }
        compute(it & 1);
        __syncthreads();
    }

    // epilogue: direct register -> global stores (float2)
    const int g  = lid >> 2;
    const int tg = lid & 3;
#pragma unroll
    for (int mi = 0; mi < 4; mi++) {
#pragma unroll
        for (int nt = 0; nt < 4; nt++) {
            const int m = bm + wm0 + mi * 16 + g;
            const int n = bn + wn0 + nt * 8 + 2 * tg;
            if (GUARD && n >= Nt) continue;
            float v0 = acc[mi][nt][0], v1 = acc[mi][nt][1];
            float v2 = acc[mi][nt][2], v3 = acc[mi][nt][3];
            if (EPI == 1) {
                const float b0 = bias[n], b1 = bias[n + 1];
                v0 += b0; v1 += b1; v2 += b0; v3 += b1;
                v0 = (v0 > 20.f) ? v0 : log1pf(__expf(v0));
                v1 = (v1 > 20.f) ? v1 : log1pf(__expf(v1));
                v2 = (v2 > 20.f) ? v2 : log1pf(__expf(v2));
                v3 = (v3 > 20.f) ? v3 : log1pf(__expf(v3));
            }
            *(float2*)&C[(size_t)m * ldc + n]       = make_float2(v0, v1);
            *(float2*)&C[(size_t)(m + 8) * ldc + n] = make_float2(v2, v3);
        }
    }
}

// ---------------------------------------------------------------------------
// fp32 -> (bf16 hi, bf16 lo) split
// ---------------------------------------------------------------------------
__global__ __launch_bounds__(256)
void cvt_split(const float* __restrict__ src, __nv_bfloat16* __restrict__ hi,
               __nv_bfloat16* __restrict__ lo, int n)
{
    int idx = blockIdx.x * 256 + threadIdx.x;
    if (idx >= n) return;
    float v = src[idx];
    __nv_bfloat16 h = __float2bfloat16(v);
    hi[idx] = h;
    lo[idx] = __float2bfloat16(v - __bfloat162float(h));
}

// extract dt columns (first 64 of each 96-wide dbc row) as split bf16
__global__ __launch_bounds__(256)
void dt_split_kernel()
{
    int idx = blockIdx.x * 256 + threadIdx.x;   // < BL*64
    int r = idx >> 6, c = idx & 63;
    float v = g_dbc[(size_t)r * DBCW + c];
    __nv_bfloat16 h = __float2bfloat16(v);
    g_dth[idx] = h;
    g_dtl[idx] = __float2bfloat16(v - __bfloat162float(h));
}

// ---------------------------------------------------------------------------
// Causal depthwise conv (k=4) + bias + SiLU; emits fp32 xc AND split bf16 xc
// ---------------------------------------------------------------------------
__global__ __launch_bounds__(256)
void conv_silu_kernel(const float* __restrict__ conv_w, const float* __restrict__ conv_b)
{
    const size_t idx = (size_t)blockIdx.x * 256 + threadIdx.x;
    if (idx >= (size_t)BL * DINNER) return;
    const int d  = (int)(idx % DINNER);
    const size_t bl = idx / DINNER;
    const int l  = (int)(bl % LENGTH);
    const size_t brow = (bl - l) * (size_t)D2;

    float acc = conv_b[d];
    const float w0 = conv_w[d*4+0], w1 = conv_w[d*4+1];
    const float w2 = conv_w[d*4+2], w3 = conv_w[d*4+3];
    const float* base = g_xz + brow + d;
    if (l >= 3) acc += w0 * base[(size_t)(l-3)*D2];
    if (l >= 2) acc += w1 * base[(size_t)(l-2)*D2];
    if (l >= 1) acc += w2 * base[(size_t)(l-1)*D2];
    acc += w3 * base[(size_t)l*D2];

    float s = acc / (1.f + __expf(-acc));
    g_xc[idx] = s;
    __nv_bfloat16 h = __float2bfloat16(s);
    g_xch[idx] = h;
    g_xcl[idx] = __float2bfloat16(s - __bfloat162float(h));
}

// ---------------------------------------------------------------------------
// Selective scan: 8 threads per (b,d) channel, 2 states each; shuffle-reduce,
// fused D*x skip + silu(z) gate; emits split-bf16 y.
// ---------------------------------------------------------------------------
__global__ __launch_bounds__(128)
void scan_kernel(const float* __restrict__ A_raw, const float* __restrict__ Dvec)
{
    const int tid = threadIdx.x;
    const int sub = tid & 7;
    const int cl  = tid >> 3;
    const int blk = blockIdx.x;
    const int b   = blk >> 7;
    const int c   = ((blk & 127) << 4) + cl;

    const float a0 = -__expf(A_raw[(2*sub+0)*DINNER + c]);
    const float a1 = -__expf(A_raw[(2*sub+1)*DINNER + c]);
    const float Dv = Dvec[c];

    float h0 = 0.f, h1 = 0.f;

    const float* dptr = g_delta + (size_t)b*LENGTH*DINNER + c;
    const float* xptr = g_xc    + (size_t)b*LENGTH*DINNER + c;
    const float* bcp  = g_dbc   + (size_t)b*LENGTH*DBCW + DTRANK + 2*sub;
    const float* zptr = g_xz    + (size_t)b*LENGTH*D2 + DINNER + c;
    __nv_bfloat16* yhp = g_yh   + (size_t)b*LENGTH*DINNER + c;
    __nv_bfloat16* ylp = g_yl   + (size_t)b*LENGTH*DINNER + c;

    for (int t = 0; t < LENGTH; ++t) {
        const float delta = *dptr;
        const float x     = *xptr;
        const float2 Bv = *(const float2*)bcp;
        const float2 Cv = *(const float2*)(bcp + DSTATE);
        const float dx = delta * x;

        h0 = fmaf(__expf(delta * a0), h0, Bv.x * dx);
        h1 = fmaf(__expf(delta * a1), h1, Bv.y * dx);

        float acc = Cv.x * h0 + Cv.y * h1;
        acc += __shfl_xor_sync(0xffffffffu, acc, 1);
        acc += __shfl_xor_sync(0xffffffffu, acc, 2);
        acc += __shfl_xor_sync(0xffffffffu, acc, 4);

        if (sub == 0) {
            const float z = *zptr;
            float y = (acc + Dv * x) * (z / (1.f + __expf(-z)));
            __nv_bfloat16 h = __float2bfloat16(y);
            *yhp = h;
            *ylp = __float2bfloat16(y - __bfloat162float(h));
        }
        dptr += DINNER; xptr += DINNER; bcp += DBCW; zptr += D2;
        yhp += DINNER; ylp += DINNER;
    }
}

// ---------------------------------------------------------------------------
extern "C" void kernel_launch(void* const* d_in, const int* in_sizes, int n_in,
                              void* d_out, int out_size)
{
    const float* x      = (const float*)d_in[0];
    const float* W_in   = (const float*)d_in[1];
    const float* conv_w = (const float*)d_in[2];
    const float* conv_b = (const float*)d_in[3];
    const float* W_x    = (const float*)d_in[4];
    const float* W_dt   = (const float*)d_in[5];
    const float* b_dt   = (const float*)d_in[6];
    const float* A_raw  = (const float*)d_in[7];
    const float* Dvec   = (const float*)d_in[8];
    const float* W_out  = (const float*)d_in[9];
    float* out = (float*)d_out;

    float *p_xz, *p_dbc, *p_delta;
    __nv_bfloat16 *p_xh,*p_xl,*p_winh,*p_winl,*p_xch,*p_xcl,*p_wxh,*p_wxl;
    __nv_bfloat16 *p_dth,*p_dtl,*p_wdth,*p_wdtl,*p_yh,*p_yl,*p_wouth,*p_woutl;
    cudaGetSymbolAddress((void**)&p_xz,    g_xz);
    cudaGetSymbolAddress((void**)&p_dbc,   g_dbc);
    cudaGetSymbolAddress((void**)&p_delta, g_delta);
    cudaGetSymbolAddress((void**)&p_xh,    g_xh);
    cudaGetSymbolAddress((void**)&p_xl,    g_xl);
    cudaGetSymbolAddress((void**)&p_winh,  g_winh);
    cudaGetSymbolAddress((void**)&p_winl,  g_winl);
    cudaGetSymbolAddress((void**)&p_xch,   g_xch);
    cudaGetSymbolAddress((void**)&p_xcl,   g_xcl);
    cudaGetSymbolAddress((void**)&p_wxh,   g_wxh);
    cudaGetSymbolAddress((void**)&p_wxl,   g_wxl);
    cudaGetSymbolAddress((void**)&p_dth,   g_dth);
    cudaGetSymbolAddress((void**)&p_dtl,   g_dtl);
    cudaGetSymbolAddress((void**)&p_wdth,  g_wdth);
    cudaGetSymbolAddress((void**)&p_wdtl,  g_wdtl);
    cudaGetSymbolAddress((void**)&p_yh,    g_yh);
    cudaGetSymbolAddress((void**)&p_yl,    g_yl);
    cudaGetSymbolAddress((void**)&p_wouth, g_wouth);
    cudaGetSymbolAddress((void**)&p_woutl, g_woutl);

    const int SMEM = 2 * STG_SZ;  // 81920
    cudaFuncSetAttribute(tgemm<0,false>, cudaFuncAttributeMaxDynamicSharedMemorySize, SMEM);
    cudaFuncSetAttribute(tgemm<0,true >, cudaFuncAttributeMaxDynamicSharedMemorySize, SMEM);
    cudaFuncSetAttribute(tgemm<1,false>, cudaFuncAttributeMaxDynamicSharedMemorySize, SMEM);

    // split conversions
    cvt_split<<<(BL*DMODEL + 255)/256, 256>>>(x,     p_xh,    p_xl,    BL*DMODEL);
    cvt_split<<<(D2*DMODEL + 255)/256, 256>>>(W_in,  p_winh,  p_winl,  D2*DMODEL);
    cvt_split<<<(DBCW*DINNER + 255)/256, 256>>>(W_x, p_wxh,   p_wxl,   DBCW*DINNER);
    cvt_split<<<(DINNER*DTRANK + 255)/256, 256>>>(W_dt, p_wdth, p_wdtl, DINNER*DTRANK);
    cvt_split<<<(DMODEL*DINNER + 255)/256, 256>>>(W_out, p_wouth, p_woutl, DMODEL*DINNER);

    // 1) xz = x @ W_in^T   (8192 x 4096, K=1024)
    tgemm<0,false><<<dim3(D2/128, BL/128), 256, SMEM>>>(
        p_xh, p_xl, DMODEL, p_winh, p_winl, DMODEL, p_xz, D2, D2, DMODEL, nullptr);

    // 2) conv + silu (emits fp32 + split bf16 xc)
    conv_silu_kernel<<<(unsigned)(((size_t)BL*DINNER + 255)/256), 256>>>(conv_w, conv_b);

    // 3) dbc = xc @ W_x^T  (8192 x 96, K=2048)
    tgemm<0,true><<<dim3(1, BL/128), 256, SMEM>>>(
        p_xch, p_xcl, DINNER, p_wxh, p_wxl, DINNER, p_dbc, DBCW, DBCW, DINNER, nullptr);

    // 4) dt columns -> split bf16
    dt_split_kernel<<<(BL*DTRANK + 255)/256, 256>>>();

    // 5) delta = softplus(dt @ W_dt^T + b_dt)  (8192 x 2048, K=64)
    tgemm<1,false><<<dim3(DINNER/128, BL/128), 256, SMEM>>>(
        p_dth, p_dtl, DTRANK, p_wdth, p_wdtl, DTRANK, p_delta, DINNER, DINNER, DTRANK, b_dt);

    // 6) selective scan + gate -> split bf16 y
    scan_kernel<<<BATCH*128, 128>>>(A_raw, Dvec);

    // 7) out = y @ W_out^T (8192 x 1024, K=2048)
    tgemm<0,false><<<dim3(DMODEL/128, BL/128), 256, SMEM>>>(
        p_yh, p_yl, DINNER, p_wouth, p_woutl, DINNER, out, DMODEL, DMODEL, DINNER, nullptr);
}

// round 6
// speedup vs baseline: 2.4125x; 1.5526x over previous
#include <cuda_runtime.h>
#include <cuda_bf16.h>
#include <cstdint>

// Problem dims (fixed)
#define BATCH   4
#define LENGTH  2048
#define DMODEL  1024
#define DINNER  2048
#define DSTATE  16
#define DTRANK  64
#define BL      (BATCH*LENGTH)        // 8192
#define D2      (2*DINNER)            // 4096
#define DBCW    (DTRANK + 2*DSTATE)   // 96

// ------------------- static scratch (no cudaMalloc allowed) -------------------
__device__ float g_xz[(size_t)BL * D2];
__device__ float g_xc[(size_t)BL * DINNER];
__device__ float g_dbc[(size_t)BL * DBCW];
__device__ float g_delta[(size_t)BL * DINNER];

__device__ __nv_bfloat16 g_xh  [(size_t)BL*DMODEL],   g_xl  [(size_t)BL*DMODEL];
__device__ __nv_bfloat16 g_winh[(size_t)D2*DMODEL],   g_winl[(size_t)D2*DMODEL];
__device__ __nv_bfloat16 g_xch [(size_t)BL*DINNER],   g_xcl [(size_t)BL*DINNER];
__device__ __nv_bfloat16 g_wxh [(size_t)DBCW*DINNER], g_wxl [(size_t)DBCW*DINNER];
__device__ __nv_bfloat16 g_dth [(size_t)BL*DTRANK],   g_dtl [(size_t)BL*DTRANK];
__device__ __nv_bfloat16 g_wdth[(size_t)DINNER*DTRANK],g_wdtl[(size_t)DINNER*DTRANK];
__device__ __nv_bfloat16 g_yh  [(size_t)BL*DINNER],   g_yl  [(size_t)BL*DINNER];
__device__ __nv_bfloat16 g_wouth[(size_t)DMODEL*DINNER],g_woutl[(size_t)DMODEL*DINNER];

// ------------------------------ PTX helpers ------------------------------
__device__ __forceinline__ uint32_t s2u(const void* p) {
    uint32_t a;
    asm("{ .reg .u64 t; cvta.to.shared.u64 t, %1; cvt.u32.u64 %0, t; }" : "=r"(a) : "l"(p));
    return a;
}
#define CP16(d, g) \
    asm volatile("cp.async.cg.shared.global [%0], [%1], 16;" :: "r"(d), "l"(g))
#define CP16Z(d, g, v) \
    asm volatile("cp.async.cg.shared.global [%0], [%1], 16, %2;" :: "r"(d), "l"(g), "r"(v))
#define CP_COMMIT() asm volatile("cp.async.commit_group;" ::: "memory")
#define CP_WAIT0()  asm volatile("cp.async.wait_group 0;" ::: "memory")

#define LDSM4(r, a) \
    asm volatile("ldmatrix.sync.aligned.m8n8.x4.shared.b16 {%0,%1,%2,%3}, [%4];" \
        : "=r"((r)[0]), "=r"((r)[1]), "=r"((r)[2]), "=r"((r)[3]) : "r"(a))

#define MMA16816(c, a, b0, b1) \
    asm volatile("mma.sync.aligned.m16n8k16.row.col.f32.bf16.bf16.f32 " \
        "{%0,%1,%2,%3}, {%4,%5,%6,%7}, {%8,%9}, {%0,%1,%2,%3};" \
        : "+f"((c)[0]), "+f"((c)[1]), "+f"((c)[2]), "+f"((c)[3]) \
        : "r"((a)[0]), "r"((a)[1]), "r"((a)[2]), "r"((a)[3]), "r"(b0), "r"(b1))

// ---------------------------------------------------------------------------
// Split-bf16 3-pass warp-MMA GEMM: C[m][n] = sum_k A[m][k]*B[n][k] (fp32 out)
// CTA tile 128x128, BK=32, 256 threads (2x4 warps, warp tile 64x32).
// 80B-padded smem rows (conflict-free ldmatrix); cp.async double buffer;
// 2 CTAs/SM. EPI: 0 plain, 1 softplus(v+bias[n]), 2 plain + dt-split (n<64).
// GUARD: bounds-check B rows / C cols against Nt.
// ---------------------------------------------------------------------------
#define STG_A_L 10240u
#define STG_B_H 20480u
#define STG_B_L 30720u
#define STG_SZ  40960u

template<int EPI, bool GUARD>
__global__ __launch_bounds__(256, 2)
void tgemm(const __nv_bfloat16* __restrict__ Ah, const __nv_bfloat16* __restrict__ Al, int lda,
           const __nv_bfloat16* __restrict__ Bh, const __nv_bfloat16* __restrict__ Bl, int ldb,
           float* __restrict__ C, int ldc, int Nt, int K,
           const float* __restrict__ bias)
{
    extern __shared__ char smem[];
    const uint32_t sb = s2u(smem);

    const int tid = threadIdx.x;
    const int lid = tid & 31;
    const int wid = tid >> 5;
    const int wm0 = (wid & 1) * 64;
    const int wn0 = (wid >> 1) * 32;

    const int bm = blockIdx.y * 128;
    const int bn = blockIdx.x * 128;

    float acc[4][4][4];
#pragma unroll
    for (int i = 0; i < 4; i++)
#pragma unroll
        for (int j = 0; j < 4; j++)
#pragma unroll
            for (int k = 0; k < 4; k++) acc[i][j][k] = 0.f;

    auto ld_stage = [&](int s, int kc) {
        const uint32_t base = sb + (uint32_t)s * STG_SZ;
        const __nv_bfloat16* pAh = Ah + (size_t)bm * lda + kc;
        const __nv_bfloat16* pAl = Al + (size_t)bm * lda + kc;
        const __nv_bfloat16* pBh = Bh + (size_t)bn * ldb + kc;
        const __nv_bfloat16* pBl = Bl + (size_t)bn * ldb + kc;
#pragma unroll
        for (int i = 0; i < 2; i++) {
            const int c   = tid + i * 256;
            const int row = c >> 2;
            const int ch  = (c & 3) * 16;
            const uint32_t o = (uint32_t)row * 80u + (uint32_t)ch;
            CP16(base + o,           (const char*)(pAh + (size_t)row * lda) + ch);
            CP16(base + STG_A_L + o, (const char*)(pAl + (size_t)row * lda) + ch);
            if (!GUARD) {
                CP16(base + STG_B_H + o, (const char*)(pBh + (size_t)row * ldb) + ch);
                CP16(base + STG_B_L + o, (const char*)(pBl + (size_t)row * ldb) + ch);
            } else {
                const uint32_t v = ((bn + row) < Nt) ? 16u : 0u;
                CP16Z(base + STG_B_H + o, (const char*)(pBh + (size_t)row * ldb) + ch, v);
                CP16Z(base + STG_B_L + o, (const char*)(pBl + (size_t)row * ldb) + ch, v);
            }
        }
    };

    const uint32_t arow  = (uint32_t)(wm0 + (lid & 15));
    const uint32_t akoff = (uint32_t)((lid >> 4) << 3);
    const uint32_t brow  = (uint32_t)(wn0 + ((lid >> 4) << 3) + (lid & 7));
    const uint32_t bkoff = (uint32_t)(((lid >> 3) & 1) << 3);

    auto compute = [&](int s) {
        const uint32_t aB = sb + (uint32_t)s * STG_SZ;
        const uint32_t bB = aB + STG_B_H;
#pragma unroll
        for (int kk = 0; kk < 2; ++kk) {
            // B fragments for this k16 slice (held across the mi loop)
            uint32_t bh[2][4], bl[2][4];
#pragma unroll
            for (int bi = 0; bi < 2; bi++) {
                const uint32_t bd = bB + (brow + bi*16) * 80u + (bkoff + kk*16) * 2u;
                LDSM4(bh[bi], bd);
                LDSM4(bl[bi], bd + STG_A_L);
            }
            // stream A fragments one M-slice at a time (keeps regs <= 128)
#pragma unroll
            for (int mi = 0; mi < 4; mi++) {
                uint32_t ah[4], al[4];
                const uint32_t ad = aB + (arow + mi*16) * 80u + (akoff + kk*16) * 2u;
                LDSM4(ah, ad);
                LDSM4(al, ad + STG_A_L);
#pragma unroll
                for (int nt = 0; nt < 4; nt++) {
                    const uint32_t b0h = bh[nt>>1][(nt&1)*2], b1h = bh[nt>>1][(nt&1)*2+1];
                    const uint32_t b0l = bl[nt>>1][(nt&1)*2], b1l = bl[nt>>1][(nt&1)*2+1];
                    MMA16816(acc[mi][nt], ah, b0h, b1h);
                    MMA16816(acc[mi][nt], ah, b0l, b1l);
                    MMA16816(acc[mi][nt], al, b0h, b1h);
                }
            }
        }
    };

    const int nit = K >> 5;
    ld_stage(0, 0);
    CP_COMMIT();
    for (int it = 0; it < nit; ++it) {
        CP_WAIT0();
        __syncthreads();   // data visible + all warps done reading the buffer we overwrite next
        if (it + 1 < nit) { ld_stage((it + 1) & 1, (it + 1) * 32); CP_COMMIT(); }
        compute(it & 1);
    }

    // epilogue
    const int g  = lid >> 2;
    const int tg = lid & 3;
#pragma unroll
    for (int mi = 0; mi < 4; mi++) {
#pragma unroll
        for (int nt = 0; nt < 4; nt++) {
            const int m = bm + wm0 + mi * 16 + g;
            const int n = bn + wn0 + nt * 8 + 2 * tg;
            if (GUARD && n >= Nt) continue;
            float v0 = acc[mi][nt][0], v1 = acc[mi][nt][1];
            float v2 = acc[mi][nt][2], v3 = acc[mi][nt][3];
            if (EPI == 1) {
                const float b0 = bias[n], b1 = bias[n + 1];
                v0 += b0; v1 += b1; v2 += b0; v3 += b1;
                v0 = (v0 > 20.f) ? v0 : log1pf(__expf(v0));
                v1 = (v1 > 20.f) ? v1 : log1pf(__expf(v1));
                v2 = (v2 > 20.f) ? v2 : log1pf(__expf(v2));
                v3 = (v3 > 20.f) ? v3 : log1pf(__expf(v3));
            }
            *(float2*)&C[(size_t)m * ldc + n]       = make_float2(v0, v1);
            *(float2*)&C[(size_t)(m + 8) * ldc + n] = make_float2(v2, v3);
            if (EPI == 2 && n < DTRANK) {
                // fused dt split: hi/lo bf16 of the first 64 columns
                __nv_bfloat16 h0 = __float2bfloat16(v0), h1 = __float2bfloat16(v1);
                __nv_bfloat16 h2 = __float2bfloat16(v2), h3 = __float2bfloat16(v3);
                __nv_bfloat16 l0 = __float2bfloat16(v0 - __bfloat162float(h0));
                __nv_bfloat16 l1 = __float2bfloat16(v1 - __bfloat162float(h1));
                __nv_bfloat16 l2 = __float2bfloat16(v2 - __bfloat162float(h2));
                __nv_bfloat16 l3 = __float2bfloat16(v3 - __bfloat162float(h3));
                *(__nv_bfloat162*)&g_dth[(size_t)m * DTRANK + n] = __nv_bfloat162(h0, h1);
                *(__nv_bfloat162*)&g_dtl[(size_t)m * DTRANK + n] = __nv_bfloat162(l0, l1);
                *(__nv_bfloat162*)&g_dth[(size_t)(m + 8) * DTRANK + n] = __nv_bfloat162(h2, h3);
                *(__nv_bfloat162*)&g_dtl[(size_t)(m + 8) * DTRANK + n] = __nv_bfloat162(l2, l3);
            }
        }
    }
}

// ---------------------------------------------------------------------------
__global__ __launch_bounds__(256)
void cvt_split(const float* __restrict__ src, __nv_bfloat16* __restrict__ hi,
               __nv_bfloat16* __restrict__ lo, int n)
{
    int idx = blockIdx.x * 256 + threadIdx.x;
    if (idx >= n) return;
    float v = src[idx];
    __nv_bfloat16 h = __float2bfloat16(v);
    hi[idx] = h;
    lo[idx] = __float2bfloat16(v - __bfloat162float(h));
}

// ---------------------------------------------------------------------------
// Causal depthwise conv (k=4) + bias + SiLU; emits fp32 xc AND split bf16 xc
// ---------------------------------------------------------------------------
__global__ __launch_bounds__(256)
void conv_silu_kernel(const float* __restrict__ conv_w, const float* __restrict__ conv_b)
{
    const size_t idx = (size_t)blockIdx.x * 256 + threadIdx.x;
    if (idx >= (size_t)BL * DINNER) return;
    const int d  = (int)(idx % DINNER);
    const size_t bl = idx / DINNER;
    const int l  = (int)(bl % LENGTH);
    const size_t brow = (bl - l) * (size_t)D2;

    float acc = conv_b[d];
    const float w0 = conv_w[d*4+0], w1 = conv_w[d*4+1];
    const float w2 = conv_w[d*4+2], w3 = conv_w[d*4+3];
    const float* base = g_xz + brow + d;
    if (l >= 3) acc += w0 * base[(size_t)(l-3)*D2];
    if (l >= 2) acc += w1 * base[(size_t)(l-2)*D2];
    if (l >= 1) acc += w2 * base[(size_t)(l-1)*D2];
    acc += w3 * base[(size_t)l*D2];

    float s = acc / (1.f + __expf(-acc));
    g_xc[idx] = s;
    __nv_bfloat16 h = __float2bfloat16(s);
    g_xch[idx] = h;
    g_xcl[idx] = __float2bfloat16(s - __bfloat162float(h));
}

// ---------------------------------------------------------------------------
// Selective scan: 8 threads/channel, 2 states each; software-pipelined loads
// (prefetch t+1 ahead of the exp/fma chain), shuffle-reduce, fused gate.
// ---------------------------------------------------------------------------
__global__ __launch_bounds__(128)
void scan_kernel(const float* __restrict__ A_raw, const float* __restrict__ Dvec)
{
    const int tid = threadIdx.x;
    const int sub = tid & 7;
    const int cl  = tid >> 3;
    const int blk = blockIdx.x;
    const int b   = blk >> 7;
    const int c   = ((blk & 127) << 4) + cl;

    const float a0 = -__expf(A_raw[(2*sub+0)*DINNER + c]);
    const float a1 = -__expf(A_raw[(2*sub+1)*DINNER + c]);
    const float Dv = Dvec[c];

    float h0 = 0.f, h1 = 0.f;

    const float* dptr = g_delta + (size_t)b*LENGTH*DINNER + c;
    const float* xptr = g_xc    + (size_t)b*LENGTH*DINNER + c;
    const float* bcp  = g_dbc   + (size_t)b*LENGTH*DBCW + DTRANK + 2*sub;
    const float* zptr = g_xz    + (size_t)b*LENGTH*D2 + DINNER + c;
    __nv_bfloat16* yhp = g_yh   + (size_t)b*LENGTH*DINNER + c;
    __nv_bfloat16* ylp = g_yl   + (size_t)b*LENGTH*DINNER + c;

    // preload t=0
    float  d_c = *dptr;
    float  x_c = *xptr;
    float2 B_c = *(const float2*)bcp;
    float2 C_c = *(const float2*)(bcp + DSTATE);
    float  z_c = (sub == 0) ? *zptr : 0.f;

    for (int t = 0; t < LENGTH; ++t) {
        // prefetch t+1 before the dependent chain of t
        float d_n = 0.f, x_n = 0.f, z_n = 0.f;
        float2 B_n = make_float2(0.f, 0.f), C_n = make_float2(0.f, 0.f);
        if (t + 1 < LENGTH) {
            d_n = dptr[DINNER];
            x_n = xptr[DINNER];
            B_n = *(const float2*)(bcp + DBCW);
            C_n = *(const float2*)(bcp + DBCW + DSTATE);
            if (sub == 0) z_n = zptr[D2];
        }

        const float dx = d_c * x_c;
        h0 = fmaf(__expf(d_c * a0), h0, B_c.x * dx);
        h1 = fmaf(__expf(d_c * a1), h1, B_c.y * dx);

        float acc = C_c.x * h0 + C_c.y * h1;
        acc += __shfl_xor_sync(0xffffffffu, acc, 1);
        acc += __shfl_xor_sync(0xffffffffu, acc, 2);
        acc += __shfl_xor_sync(0xffffffffu, acc, 4);

        if (sub == 0) {
            float y = (acc + Dv * x_c) * (z_c / (1.f + __expf(-z_c)));
            __nv_bfloat16 h = __float2bfloat16(y);
            *yhp = h;
            *ylp = __float2bfloat16(y - __bfloat162float(h));
        }

        d_c = d_n; x_c = x_n; B_c = B_n; C_c = C_n; z_c = z_n;
        dptr += DINNER; xptr += DINNER; bcp += DBCW; zptr += D2;
        yhp += DINNER; ylp += DINNER;
    }
}

// ---------------------------------------------------------------------------
extern "C" void kernel_launch(void* const* d_in, const int* in_sizes, int n_in,
                              void* d_out, int out_size)
{
    const float* x      = (const float*)d_in[0];
    const float* W_in   = (const float*)d_in[1];
    const float* conv_w = (const float*)d_in[2];
    const float* conv_b = (const float*)d_in[3];
    const float* W_x    = (const float*)d_in[4];
    const float* W_dt   = (const float*)d_in[5];
    const float* b_dt   = (const float*)d_in[6];
    const float* A_raw  = (const float*)d_in[7];
    const float* Dvec   = (const float*)d_in[8];
    const float* W_out  = (const float*)d_in[9];
    float* out = (float*)d_out;

    float *p_xz, *p_dbc, *p_delta;
    __nv_bfloat16 *p_xh,*p_xl,*p_winh,*p_winl,*p_xch,*p_xcl,*p_wxh,*p_wxl;
    __nv_bfloat16 *p_dth,*p_dtl,*p_wdth,*p_wdtl,*p_yh,*p_yl,*p_wouth,*p_woutl;
    cudaGetSymbolAddress((void**)&p_xz,    g_xz);
    cudaGetSymbolAddress((void**)&p_dbc,   g_dbc);
    cudaGetSymbolAddress((void**)&p_delta, g_delta);
    cudaGetSymbolAddress((void**)&p_xh,    g_xh);
    cudaGetSymbolAddress((void**)&p_xl,    g_xl);
    cudaGetSymbolAddress((void**)&p_winh,  g_winh);
    cudaGetSymbolAddress((void**)&p_winl,  g_winl);
    cudaGetSymbolAddress((void**)&p_xch,   g_xch);
    cudaGetSymbolAddress((void**)&p_xcl,   g_xcl);
    cudaGetSymbolAddress((void**)&p_wxh,   g_wxh);
    cudaGetSymbolAddress((void**)&p_wxl,   g_wxl);
    cudaGetSymbolAddress((void**)&p_dth,   g_dth);
    cudaGetSymbolAddress((void**)&p_dtl,   g_dtl);
    cudaGetSymbolAddress((void**)&p_wdth,  g_wdth);
    cudaGetSymbolAddress((void**)&p_wdtl,  g_wdtl);
    cudaGetSymbolAddress((void**)&p_yh,    g_yh);
    cudaGetSymbolAddress((void**)&p_yl,    g_yl);
    cudaGetSymbolAddress((void**)&p_wouth, g_wouth);
    cudaGetSymbolAddress((void**)&p_woutl, g_woutl);

    const int SMEM = 2 * STG_SZ;  // 81920
    cudaFuncSetAttribute(tgemm<0,false>, cudaFuncAttributeMaxDynamicSharedMemorySize, SMEM);
    cudaFuncSetAttribute(tgemm<2,true >, cudaFuncAttributeMaxDynamicSharedMemorySize, SMEM);
    cudaFuncSetAttribute(tgemm<1,false>, cudaFuncAttributeMaxDynamicSharedMemorySize, SMEM);

    // split conversions
    cvt_split<<<(BL*DMODEL + 255)/256, 256>>>(x,     p_xh,    p_xl,    BL*DMODEL);
    cvt_split<<<(D2*DMODEL + 255)/256, 256>>>(W_in,  p_winh,  p_winl,  D2*DMODEL);
    cvt_split<<<(DBCW*DINNER + 255)/256, 256>>>(W_x, p_wxh,   p_wxl,   DBCW*DINNER);
    cvt_split<<<(DINNER*DTRANK + 255)/256, 256>>>(W_dt, p_wdth, p_wdtl, DINNER*DTRANK);
    cvt_split<<<(DMODEL*DINNER + 255)/256, 256>>>(W_out, p_wouth, p_woutl, DMODEL*DINNER);

    // 1) xz = x @ W_in^T   (8192 x 4096, K=1024)
    tgemm<0,false><<<dim3(D2/128, BL/128), 256, SMEM>>>(
        p_xh, p_xl, DMODEL, p_winh, p_winl, DMODEL, p_xz, D2, D2, DMODEL, nullptr);

    // 2) conv + silu (emits fp32 + split bf16 xc)
    conv_silu_kernel<<<(unsigned)(((size_t)BL*DINNER + 255)/256), 256>>>(conv_w, conv_b);

    // 3) dbc = xc @ W_x^T  (8192 x 96, K=2048); dt split fused in epilogue
    tgemm<2,true><<<dim3(1, BL/128), 256, SMEM>>>(
        p_xch, p_xcl, DINNER, p_wxh, p_wxl, DINNER, p_dbc, DBCW, DBCW, DINNER, nullptr);

    // 4) delta = softplus(dt @ W_dt^T + b_dt)  (8192 x 2048, K=64)
    tgemm<1,false><<<dim3(DINNER/128, BL/128), 256, SMEM>>>(
        p_dth, p_dtl, DTRANK, p_wdth, p_wdtl, DTRANK, p_delta, DINNER, DINNER, DTRANK, b_dt);

    // 5) selective scan + gate -> split bf16 y
    scan_kernel<<<BATCH*128, 128>>>(A_raw, Dvec);

    // 6) out = y @ W_out^T (8192 x 1024, K=2048)
    tgemm<0,false><<<dim3(DMODEL/128, BL/128), 256, SMEM>>>(
        p_yh, p_yl, DINNER, p_wouth, p_woutl, DINNER, out, DMODEL, DMODEL, DINNER, nullptr);
}

// round 7
// speedup vs baseline: 2.4830x; 1.0292x over previous
#include <cuda_runtime.h>
#include <cuda_fp16.h>
#include <cstdint>

// Problem dims (fixed)
#define BATCH   4
#define LENGTH  2048
#define DMODEL  1024
#define DINNER  2048
#define DSTATE  16
#define DTRANK  64
#define BL      (BATCH*LENGTH)        // 8192
#define D2      (2*DINNER)            // 4096
#define DBCW    (DTRANK + 2*DSTATE)   // 96

// ------------------- static scratch (no cudaMalloc allowed) -------------------
__device__ float g_xz[(size_t)BL * D2];
__device__ float g_xc[(size_t)BL * DINNER];
__device__ float g_dbc[(size_t)BL * DBCW];
__device__ float g_delta[(size_t)BL * DINNER];

__device__ __half g_xh  [(size_t)BL*DMODEL],   g_xl  [(size_t)BL*DMODEL];
__device__ __half g_winh[(size_t)D2*DMODEL],   g_winl[(size_t)D2*DMODEL];
__device__ __half g_xch [(size_t)BL*DINNER],   g_xcl [(size_t)BL*DINNER];
__device__ __half g_wxh [(size_t)DBCW*DINNER], g_wxl [(size_t)DBCW*DINNER];
__device__ __half g_dth [(size_t)BL*DTRANK],   g_dtl [(size_t)BL*DTRANK];
__device__ __half g_wdth[(size_t)DINNER*DTRANK],g_wdtl[(size_t)DINNER*DTRANK];
__device__ __half g_yh  [(size_t)BL*DINNER],   g_yl  [(size_t)BL*DINNER];
__device__ __half g_wouth[(size_t)DMODEL*DINNER],g_woutl[(size_t)DMODEL*DINNER];

// ------------------------------ PTX helpers ------------------------------
__device__ __forceinline__ uint32_t s2u(const void* p) {
    uint32_t a;
    asm("{ .reg .u64 t; cvta.to.shared.u64 t, %1; cvt.u32.u64 %0, t; }" : "=r"(a) : "l"(p));
    return a;
}
#define CP16(d, g) \
    asm volatile("cp.async.cg.shared.global [%0], [%1], 16;" :: "r"(d), "l"(g))
#define CP16Z(d, g, v) \
    asm volatile("cp.async.cg.shared.global [%0], [%1], 16, %2;" :: "r"(d), "l"(g), "r"(v))
#define CP_COMMIT() asm volatile("cp.async.commit_group;" ::: "memory")
#define CP_WAIT0()  asm volatile("cp.async.wait_group 0;" ::: "memory")

#define LDSM4(r, a) \
    asm volatile("ldmatrix.sync.aligned.m8n8.x4.shared.b16 {%0,%1,%2,%3}, [%4];" \
        : "=r"((r)[0]), "=r"((r)[1]), "=r"((r)[2]), "=r"((r)[3]) : "r"(a))

#define MMA16816(c, a, b0, b1) \
    asm volatile("mma.sync.aligned.m16n8k16.row.col.f32.f16.f16.f32 " \
        "{%0,%1,%2,%3}, {%4,%5,%6,%7}, {%8,%9}, {%0,%1,%2,%3};" \
        : "+f"((c)[0]), "+f"((c)[1]), "+f"((c)[2]), "+f"((c)[3]) \
        : "r"((a)[0]), "r"((a)[1]), "r"((a)[2]), "r"((a)[3]), "r"(b0), "r"(b1))

// ---------------------------------------------------------------------------
// Split-fp16 warp-MMA GEMM: C[m][n] = sum_k A[m][k]*B[n][k] (fp32 out)
// PASSES=3: Ah*Bh + Ah*Bl + Al*Bh.  PASSES=2: Ah*Bh + Al*Bh (B single fp16).
// CTA tile 128x128, BK=32, 256 threads (2x4 warps, 64x32 warp tile),
// 80B-padded smem rows, cp.async double buffer, 2 CTAs/SM.
// EPI: 0 plain, 1 softplus(v+bias[n]), 2 plain + fused fp16 dt-split (n<64).
// GUARD: bounds-check B rows / C cols against Nt.
// ---------------------------------------------------------------------------
#define STG_A_L 10240u
#define STG_B_H 20480u
#define STG_B_L 30720u
#define STG_SZ  40960u

template<int PASSES, int EPI, bool GUARD>
__global__ __launch_bounds__(256, 2)
void tgemm(const __half* __restrict__ Ah, const __half* __restrict__ Al, int lda,
           const __half* __restrict__ Bh, const __half* __restrict__ Bl, int ldb,
           float* __restrict__ C, int ldc, int Nt, int K,
           const float* __restrict__ bias)
{
    extern __shared__ char smem[];
    const uint32_t sb = s2u(smem);

    const int tid = threadIdx.x;
    const int lid = tid & 31;
    const int wid = tid >> 5;
    const int wm0 = (wid & 1) * 64;
    const int wn0 = (wid >> 1) * 32;

    const int bm = blockIdx.y * 128;
    const int bn = blockIdx.x * 128;

    float acc[4][4][4];
#pragma unroll
    for (int i = 0; i < 4; i++)
#pragma unroll
        for (int j = 0; j < 4; j++)
#pragma unroll
            for (int k = 0; k < 4; k++) acc[i][j][k] = 0.f;

    auto ld_stage = [&](int s, int kc) {
        const uint32_t base = sb + (uint32_t)s * STG_SZ;
        const __half* pAh = Ah + (size_t)bm * lda + kc;
        const __half* pAl = Al + (size_t)bm * lda + kc;
        const __half* pBh = Bh + (size_t)bn * ldb + kc;
        const __half* pBl = Bl + (size_t)bn * ldb + kc;
#pragma unroll
        for (int i = 0; i < 2; i++) {
            const int c   = tid + i * 256;
            const int row = c >> 2;
            const int ch  = (c & 3) * 16;
            const uint32_t o = (uint32_t)row * 80u + (uint32_t)ch;
            CP16(base + o,           (const char*)(pAh + (size_t)row * lda) + ch);
            CP16(base + STG_A_L + o, (const char*)(pAl + (size_t)row * lda) + ch);
            if (!GUARD) {
                CP16(base + STG_B_H + o, (const char*)(pBh + (size_t)row * ldb) + ch);
                if (PASSES == 3)
                    CP16(base + STG_B_L + o, (const char*)(pBl + (size_t)row * ldb) + ch);
            } else {
                const uint32_t v = ((bn + row) < Nt) ? 16u : 0u;
                CP16Z(base + STG_B_H + o, (const char*)(pBh + (size_t)row * ldb) + ch, v);
                if (PASSES == 3)
                    CP16Z(base + STG_B_L + o, (const char*)(pBl + (size_t)row * ldb) + ch, v);
            }
        }
    };

    const uint32_t arow  = (uint32_t)(wm0 + (lid & 15));
    const uint32_t akoff = (uint32_t)((lid >> 4) << 3);
    const uint32_t brow  = (uint32_t)(wn0 + ((lid >> 4) << 3) + (lid & 7));
    const uint32_t bkoff = (uint32_t)(((lid >> 3) & 1) << 3);

    auto compute = [&](int s) {
        const uint32_t aB = sb + (uint32_t)s * STG_SZ;
        const uint32_t bB = aB + STG_B_H;
#pragma unroll
        for (int kk = 0; kk < 2; ++kk) {
            uint32_t bh[2][4], bl[2][4];
#pragma unroll
            for (int bi = 0; bi < 2; bi++) {
                const uint32_t bd = bB + (brow + bi*16) * 80u + (bkoff + kk*16) * 2u;
                LDSM4(bh[bi], bd);
                if (PASSES == 3) LDSM4(bl[bi], bd + STG_A_L);
            }
#pragma unroll
            for (int mi = 0; mi < 4; mi++) {
                uint32_t ah[4], al[4];
                const uint32_t ad = aB + (arow + mi*16) * 80u + (akoff + kk*16) * 2u;
                LDSM4(ah, ad);
                LDSM4(al, ad + STG_A_L);
#pragma unroll
                for (int nt = 0; nt < 4; nt++) {
                    const uint32_t b0h = bh[nt>>1][(nt&1)*2], b1h = bh[nt>>1][(nt&1)*2+1];
                    MMA16816(acc[mi][nt], ah, b0h, b1h);
                    MMA16816(acc[mi][nt], al, b0h, b1h);
                    if (PASSES == 3) {
                        const uint32_t b0l = bl[nt>>1][(nt&1)*2], b1l = bl[nt>>1][(nt&1)*2+1];
                        MMA16816(acc[mi][nt], ah, b0l, b1l);
                    }
                }
            }
        }
    };

    const int nit = K >> 5;
    ld_stage(0, 0);
    CP_COMMIT();
    for (int it = 0; it < nit; ++it) {
        CP_WAIT0();
        __syncthreads();
        if (it + 1 < nit) { ld_stage((it + 1) & 1, (it + 1) * 32); CP_COMMIT(); }
        compute(it & 1);
    }

    // epilogue
    const int g  = lid >> 2;
    const int tg = lid & 3;
#pragma unroll
    for (int mi = 0; mi < 4; mi++) {
#pragma unroll
        for (int nt = 0; nt < 4; nt++) {
            const int m = bm + wm0 + mi * 16 + g;
            const int n = bn + wn0 + nt * 8 + 2 * tg;
            if (GUARD && n >= Nt) continue;
            float v0 = acc[mi][nt][0], v1 = acc[mi][nt][1];
            float v2 = acc[mi][nt][2], v3 = acc[mi][nt][3];
            if (EPI == 1) {
                const float b0 = bias[n], b1 = bias[n + 1];
                v0 += b0; v1 += b1; v2 += b0; v3 += b1;
                v0 = (v0 > 20.f) ? v0 : log1pf(__expf(v0));
                v1 = (v1 > 20.f) ? v1 : log1pf(__expf(v1));
                v2 = (v2 > 20.f) ? v2 : log1pf(__expf(v2));
                v3 = (v3 > 20.f) ? v3 : log1pf(__expf(v3));
            }
            *(float2*)&C[(size_t)m * ldc + n]       = make_float2(v0, v1);
            *(float2*)&C[(size_t)(m + 8) * ldc + n] = make_float2(v2, v3);
            if (EPI == 2 && n < DTRANK) {
                __half h0 = __float2half_rn(v0), h1 = __float2half_rn(v1);
                __half h2 = __float2half_rn(v2), h3 = __float2half_rn(v3);
                __half l0 = __float2half_rn(v0 - __half2float(h0));
                __half l1 = __float2half_rn(v1 - __half2float(h1));
                __half l2 = __float2half_rn(v2 - __half2float(h2));
                __half l3 = __float2half_rn(v3 - __half2float(h3));
                *(__half2*)&g_dth[(size_t)m * DTRANK + n] = __half2(h0, h1);
                *(__half2*)&g_dtl[(size_t)m * DTRANK + n] = __half2(l0, l1);
                *(__half2*)&g_dth[(size_t)(m + 8) * DTRANK + n] = __half2(h2, h3);
                *(__half2*)&g_dtl[(size_t)(m + 8) * DTRANK + n] = __half2(l2, l3);
            }
        }
    }
}

// ---------------------------------------------------------------------------
// One launch for all five fp32 -> (fp16 hi, fp16 lo) weight/input splits.
// Segment bounds are compile-time constants.
// ---------------------------------------------------------------------------
#define N0 (BL*DMODEL)         // x        8388608
#define N1 (D2*DMODEL)         // W_in     4194304
#define N2 (DBCW*DINNER)       // W_x       196608
#define N3 (DINNER*DTRANK)     // W_dt      131072
#define N4 (DMODEL*DINNER)     // W_out    2097152
#define NT5 (N0+N1+N2+N3+N4)   // 15007744

__global__ __launch_bounds__(256)
void cvt_split5(const float* __restrict__ s0, const float* __restrict__ s1,
                const float* __restrict__ s2, const float* __restrict__ s3,
                const float* __restrict__ s4)
{
    int idx = blockIdx.x * 256 + threadIdx.x;
    if (idx >= NT5) return;
    const float* src; __half *hi, *lo; int off;
    if      (idx < N0)          { src = s0; hi = g_xh;    lo = g_xl;    off = idx; }
    else if (idx < N0+N1)       { src = s1; hi = g_winh;  lo = g_winl;  off = idx - N0; }
    else if (idx < N0+N1+N2)    { src = s2; hi = g_wxh;   lo = g_wxl;   off = idx - N0-N1; }
    else if (idx < N0+N1+N2+N3) { src = s3; hi = g_wdth;  lo = g_wdtl;  off = idx - N0-N1-N2; }
    else                        { src = s4; hi = g_wouth; lo = g_woutl; off = idx - N0-N1-N2-N3; }
    float v = src[off];
    __half h = __float2half_rn(v);
    hi[off] = h;
    lo[off] = __float2half_rn(v - __half2float(h));
}

// ---------------------------------------------------------------------------
// Causal depthwise conv (k=4) + bias + SiLU; emits fp32 xc AND split fp16 xc
// ---------------------------------------------------------------------------
__global__ __launch_bounds__(256)
void conv_silu_kernel(const float* __restrict__ conv_w, const float* __restrict__ conv_b)
{
    const size_t idx = (size_t)blockIdx.x * 256 + threadIdx.x;
    if (idx >= (size_t)BL * DINNER) return;
    const int d  = (int)(idx % DINNER);
    const size_t bl = idx / DINNER;
    const int l  = (int)(bl % LENGTH);
    const size_t brow = (bl - l) * (size_t)D2;

    float acc = conv_b[d];
    const float w0 = conv_w[d*4+0], w1 = conv_w[d*4+1];
    const float w2 = conv_w[d*4+2], w3 = conv_w[d*4+3];
    const float* base = g_xz + brow + d;
    if (l >= 3) acc += w0 * base[(size_t)(l-3)*D2];
    if (l >= 2) acc += w1 * base[(size_t)(l-2)*D2];
    if (l >= 1) acc += w2 * base[(size_t)(l-1)*D2];
    acc += w3 * base[(size_t)l*D2];

    float s = acc / (1.f + __expf(-acc));
    g_xc[idx] = s;
    __half h = __float2half_rn(s);
    g_xch[idx] = h;
    g_xcl[idx] = __float2half_rn(s - __half2float(h));
}

// ---------------------------------------------------------------------------
// Selective scan: 8 threads/channel, 2 states each, software-pipelined loads,
// shuffle-reduce, fused D*x skip + silu(z) gate; emits split-fp16 y.
// ---------------------------------------------------------------------------
__global__ __launch_bounds__(128)
void scan_kernel(const float* __restrict__ A_raw, const float* __restrict__ Dvec)
{
    const int tid = threadIdx.x;
    const int sub = tid & 7;
    const int cl  = tid >> 3;
    const int blk = blockIdx.x;
    const int b   = blk >> 7;
    const int c   = ((blk & 127) << 4) + cl;

    const float a0 = -__expf(A_raw[(2*sub+0)*DINNER + c]);
    const float a1 = -__expf(A_raw[(2*sub+1)*DINNER + c]);
    const float Dv = Dvec[c];

    float h0 = 0.f, h1 = 0.f;

    const float* dptr = g_delta + (size_t)b*LENGTH*DINNER + c;
    const float* xptr = g_xc    + (size_t)b*LENGTH*DINNER + c;
    const float* bcp  = g_dbc   + (size_t)b*LENGTH*DBCW + DTRANK + 2*sub;
    const float* zptr = g_xz    + (size_t)b*LENGTH*D2 + DINNER + c;
    __half* yhp = g_yh + (size_t)b*LENGTH*DINNER + c;
    __half* ylp = g_yl + (size_t)b*LENGTH*DINNER + c;

    float  d_c = *dptr;
    float  x_c = *xptr;
    float2 B_c = *(const float2*)bcp;
    float2 C_c = *(const float2*)(bcp + DSTATE);
    float  z_c = (sub == 0) ? *zptr : 0.f;

    for (int t = 0; t < LENGTH; ++t) {
        float d_n = 0.f, x_n = 0.f, z_n = 0.f;
        float2 B_n = make_float2(0.f, 0.f), C_n = make_float2(0.f, 0.f);
        if (t + 1 < LENGTH) {
            d_n = dptr[DINNER];
            x_n = xptr[DINNER];
            B_n = *(const float2*)(bcp + DBCW);
            C_n = *(const float2*)(bcp + DBCW + DSTATE);
            if (sub == 0) z_n = zptr[D2];
        }

        const float dx = d_c * x_c;
        h0 = fmaf(__expf(d_c * a0), h0, B_c.x * dx);
        h1 = fmaf(__expf(d_c * a1), h1, B_c.y * dx);

        float acc = C_c.x * h0 + C_c.y * h1;
        acc += __shfl_xor_sync(0xffffffffu, acc, 1);
        acc += __shfl_xor_sync(0xffffffffu, acc, 2);
        acc += __shfl_xor_sync(0xffffffffu, acc, 4);

        if (sub == 0) {
            float y = (acc + Dv * x_c) * (z_c / (1.f + __expf(-z_c)));
            __half h = __float2half_rn(y);
            *yhp = h;
            *ylp = __float2half_rn(y - __half2float(h));
        }

        d_c = d_n; x_c = x_n; B_c = B_n; C_c = C_n; z_c = z_n;
        dptr += DINNER; xptr += DINNER; bcp += DBCW; zptr += D2;
        yhp += DINNER; ylp += DINNER;
    }
}

// ---------------------------------------------------------------------------
extern "C" void kernel_launch(void* const* d_in, const int* in_sizes, int n_in,
                              void* d_out, int out_size)
{
    const float* x      = (const float*)d_in[0];
    const float* W_in   = (const float*)d_in[1];
    const float* conv_w = (const float*)d_in[2];
    const float* conv_b = (const float*)d_in[3];
    const float* W_x    = (const float*)d_in[4];
    const float* W_dt   = (const float*)d_in[5];
    const float* b_dt   = (const float*)d_in[6];
    const float* A_raw  = (const float*)d_in[7];
    const float* Dvec   = (const float*)d_in[8];
    const float* W_out  = (const float*)d_in[9];
    float* out = (float*)d_out;

    float *p_xz, *p_dbc, *p_delta;
    __half *p_xh,*p_xl,*p_winh,*p_winl,*p_xch,*p_xcl,*p_wxh,*p_wxl;
    __half *p_dth,*p_dtl,*p_wdth,*p_wdtl,*p_yh,*p_yl,*p_wouth,*p_woutl;
    cudaGetSymbolAddress((void**)&p_xz,    g_xz);
    cudaGetSymbolAddress((void**)&p_dbc,   g_dbc);
    cudaGetSymbolAddress((void**)&p_delta, g_delta);
    cudaGetSymbolAddress((void**)&p_xh,    g_xh);
    cudaGetSymbolAddress((void**)&p_xl,    g_xl);
    cudaGetSymbolAddress((void**)&p_winh,  g_winh);
    cudaGetSymbolAddress((void**)&p_winl,  g_winl);
    cudaGetSymbolAddress((void**)&p_xch,   g_xch);
    cudaGetSymbolAddress((void**)&p_xcl,   g_xcl);
    cudaGetSymbolAddress((void**)&p_wxh,   g_wxh);
    cudaGetSymbolAddress((void**)&p_wxl,   g_wxl);
    cudaGetSymbolAddress((void**)&p_dth,   g_dth);
    cudaGetSymbolAddress((void**)&p_dtl,   g_dtl);
    cudaGetSymbolAddress((void**)&p_wdth,  g_wdth);
    cudaGetSymbolAddress((void**)&p_wdtl,  g_wdtl);
    cudaGetSymbolAddress((void**)&p_yh,    g_yh);
    cudaGetSymbolAddress((void**)&p_yl,    g_yl);
    cudaGetSymbolAddress((void**)&p_wouth, g_wouth);
    cudaGetSymbolAddress((void**)&p_woutl, g_woutl);

    const int SMEM = 2 * STG_SZ;  // 81920
    cudaFuncSetAttribute(tgemm<3,0,false>, cudaFuncAttributeMaxDynamicSharedMemorySize, SMEM);
    cudaFuncSetAttribute(tgemm<3,2,true >, cudaFuncAttributeMaxDynamicSharedMemorySize, SMEM);
    cudaFuncSetAttribute(tgemm<3,1,false>, cudaFuncAttributeMaxDynamicSharedMemorySize, SMEM);
    cudaFuncSetAttribute(tgemm<2,0,false>, cudaFuncAttributeMaxDynamicSharedMemorySize, SMEM);

    // 0) all input/weight splits in one launch
    cvt_split5<<<(NT5 + 255)/256, 256>>>(x, W_in, W_x, W_dt, W_out);

    // 1) xz = x @ W_in^T   (8192 x 4096, K=1024), 3-pass
    tgemm<3,0,false><<<dim3(D2/128, BL/128), 256, SMEM>>>(
        p_xh, p_xl, DMODEL, p_winh, p_winl, DMODEL, p_xz, D2, D2, DMODEL, nullptr);

    // 2) conv + silu (emits fp32 + split fp16 xc)
    conv_silu_kernel<<<(unsigned)(((size_t)BL*DINNER + 255)/256), 256>>>(conv_w, conv_b);

    // 3) dbc = xc @ W_x^T  (8192 x 96, K=2048), 3-pass, fused dt split
    tgemm<3,2,true><<<dim3(1, BL/128), 256, SMEM>>>(
        p_xch, p_xcl, DINNER, p_wxh, p_wxl, DINNER, p_dbc, DBCW, DBCW, DINNER, nullptr);

    // 4) delta = softplus(dt @ W_dt^T + b_dt)  (8192 x 2048, K=64), 3-pass
    tgemm<3,1,false><<<dim3(DINNER/128, BL/128), 256, SMEM>>>(
        p_dth, p_dtl, DTRANK, p_wdth, p_wdtl, DTRANK, p_delta, DINNER, DINNER, DTRANK, b_dt);

    // 5) selective scan + gate -> split fp16 y
    scan_kernel<<<BATCH*128, 128>>>(A_raw, Dvec);

    // 6) out = y @ W_out^T (8192 x 1024, K=2048), 2-pass (terminal error)
    tgemm<2,0,false><<<dim3(DMODEL/128, BL/128), 256, SMEM>>>(
        p_yh, p_yl, DINNER, p_wouth, p_woutl, DINNER, out, DMODEL, DMODEL, DINNER, nullptr);
}

// round 10
// speedup vs baseline: 2.7435x; 1.1049x over previous
#include <cuda_runtime.h>
#include <cuda_fp16.h>
#include <cstdint>

// Problem dims (fixed)
#define BATCH   4
#define LENGTH  2048
#define DMODEL  1024
#define DINNER  2048
#define DSTATE  16
#define DTRANK  64
#define BL      (BATCH*LENGTH)        // 8192
#define D2      (2*DINNER)            // 4096
#define DBCW    (DTRANK + 2*DSTATE)   // 96

// ------------------- static scratch (no cudaMalloc allowed) -------------------
__device__ float g_xz[(size_t)BL * D2];
__device__ float g_xc[(size_t)BL * DINNER];
__device__ float g_dbc[(size_t)BL * DBCW];
__device__ float g_delta[(size_t)BL * DINNER];

__device__ __half g_xh  [(size_t)BL*DMODEL],   g_xl  [(size_t)BL*DMODEL];
__device__ __half g_winh[(size_t)D2*DMODEL];
__device__ __half g_xch [(size_t)BL*DINNER],   g_xcl [(size_t)BL*DINNER];
__device__ __half g_wxh [(size_t)DBCW*DINNER];
__device__ __half g_dth [(size_t)BL*DTRANK],   g_dtl [(size_t)BL*DTRANK];
__device__ __half g_wdth[(size_t)DINNER*DTRANK];
__device__ __half g_yh  [(size_t)BL*DINNER],   g_yl  [(size_t)BL*DINNER];
__device__ __half g_wouth[(size_t)DMODEL*DINNER];

// ------------------------------ PTX helpers ------------------------------
__device__ __forceinline__ uint32_t s2u(const void* p) {
    uint32_t a;
    asm("{ .reg .u64 t; cvta.to.shared.u64 t, %1; cvt.u32.u64 %0, t; }" : "=r"(a) : "l"(p));
    return a;
}
#define CP16(d, g) \
    asm volatile("cp.async.cg.shared.global [%0], [%1], 16;" :: "r"(d), "l"(g))
#define CP16Z(d, g, v) \
    asm volatile("cp.async.cg.shared.global [%0], [%1], 16, %2;" :: "r"(d), "l"(g), "r"(v))
#define CP_COMMIT() asm volatile("cp.async.commit_group;" ::: "memory")
#define CP_WAIT1()  asm volatile("cp.async.wait_group 1;" ::: "memory")

#define LDSM4(r, a) \
    asm volatile("ldmatrix.sync.aligned.m8n8.x4.shared.b16 {%0,%1,%2,%3}, [%4];" \
        : "=r"((r)[0]), "=r"((r)[1]), "=r"((r)[2]), "=r"((r)[3]) : "r"(a))

#define MMA16816(c, a, b0, b1) \
    asm volatile("mma.sync.aligned.m16n8k16.row.col.f32.f16.f16.f32 " \
        "{%0,%1,%2,%3}, {%4,%5,%6,%7}, {%8,%9}, {%0,%1,%2,%3};" \
        : "+f"((c)[0]), "+f"((c)[1]), "+f"((c)[2]), "+f"((c)[3]) \
        : "r"((a)[0]), "r"((a)[1]), "r"((a)[2]), "r"((a)[3]), "r"(b0), "r"(b1))

// ---------------------------------------------------------------------------
// 2-pass split-fp16 warp-MMA GEMM: C[m][n] = sum_k A[m][k]*B[n][k] (fp32 out)
// Passes: Ah*Bh + Al*Bh (A split, B single fp16).
// CTA tile MTILE x 128, BK=32, 256 threads (2x4 warps), 3-stage cp.async
// pipeline (wait_group 1), 80B-padded smem rows, 2 CTAs/SM.
// EPI: 0 plain, 1 softplus(v+bias[n]), 2 plain + fused fp16 dt-split (n<64).
// GUARD: bounds-check B rows / C cols against Nt.
// ---------------------------------------------------------------------------
template<int MTILE, int EPI, bool GUARD>
__global__ __launch_bounds__(256, 2)
void tgemm(const __half* __restrict__ Ah, const __half* __restrict__ Al, int lda,
           const __half* __restrict__ Bh, int ldb,
           float* __restrict__ C, int ldc, int Nt, int K,
           const float* __restrict__ bias)
{
    constexpr uint32_t OFF_AL = (uint32_t)MTILE * 80u;
    constexpr uint32_t OFF_B  = 2u * (uint32_t)MTILE * 80u;
    constexpr uint32_t STG    = OFF_B + 128u * 80u;
    constexpr int MI = MTILE / 32;        // m-fragments per warp

    extern __shared__ char smem[];
    const uint32_t sb = s2u(smem);

    const int tid = threadIdx.x;
    const int lid = tid & 31;
    const int wid = tid >> 5;
    const int wm0 = (wid & 1) * (MTILE / 2);
    const int wn0 = (wid >> 1) * 32;

    const int bm = blockIdx.y * MTILE;
    const int bn = blockIdx.x * 128;

    float acc[MI][4][4];
#pragma unroll
    for (int i = 0; i < MI; i++)
#pragma unroll
        for (int j = 0; j < 4; j++)
#pragma unroll
            for (int k = 0; k < 4; k++) acc[i][j][k] = 0.f;

    auto ld_stage = [&](int s, int kc) {
        const uint32_t base = sb + (uint32_t)s * STG;
        const __half* pAh = Ah + (size_t)bm * lda + kc;
        const __half* pAl = Al + (size_t)bm * lda + kc;
        const __half* pBh = Bh + (size_t)bn * ldb + kc;
#pragma unroll
        for (int i = 0; i < (MTILE * 4) / 256; ++i) {
            const int c   = tid + i * 256;
            const int row = c >> 2;
            const int ch  = (c & 3) * 16;
            const uint32_t o = (uint32_t)row * 80u + (uint32_t)ch;
            CP16(base + o,          (const char*)(pAh + (size_t)row * lda) + ch);
            CP16(base + OFF_AL + o, (const char*)(pAl + (size_t)row * lda) + ch);
        }
#pragma unroll
        for (int i = 0; i < 2; ++i) {
            const int c   = tid + i * 256;
            const int row = c >> 2;
            const int ch  = (c & 3) * 16;
            const uint32_t o = (uint32_t)row * 80u + (uint32_t)ch;
            if (!GUARD) {
                CP16(base + OFF_B + o, (const char*)(pBh + (size_t)row * ldb) + ch);
            } else {
                const uint32_t v = ((bn + row) < Nt) ? 16u : 0u;
                CP16Z(base + OFF_B + o, (const char*)(pBh + (size_t)row * ldb) + ch, v);
            }
        }
    };

    const uint32_t arow  = (uint32_t)(wm0 + (lid & 15));
    const uint32_t akoff = (uint32_t)((lid >> 4) << 3);
    const uint32_t brow  = (uint32_t)(wn0 + ((lid >> 4) << 3) + (lid & 7));
    const uint32_t bkoff = (uint32_t)(((lid >> 3) & 1) << 3);

    auto compute = [&](int s) {
        const uint32_t aB = sb + (uint32_t)s * STG;
        const uint32_t bB = aB + OFF_B;
#pragma unroll
        for (int kk = 0; kk < 2; ++kk) {
            uint32_t bh[2][4];
#pragma unroll
            for (int bi = 0; bi < 2; bi++) {
                const uint32_t bd = bB + (brow + bi*16) * 80u + (bkoff + kk*16) * 2u;
                LDSM4(bh[bi], bd);
            }
#pragma unroll
            for (int mi = 0; mi < MI; mi++) {
                uint32_t ah[4], al[4];
                const uint32_t ad = aB + (arow + mi*16) * 80u + (akoff + kk*16) * 2u;
                LDSM4(ah, ad);
                LDSM4(al, ad + OFF_AL);
#pragma unroll
                for (int nt = 0; nt < 4; nt++) {
                    const uint32_t b0 = bh[nt>>1][(nt&1)*2], b1 = bh[nt>>1][(nt&1)*2+1];
                    MMA16816(acc[mi][nt], ah, b0, b1);
                    MMA16816(acc[mi][nt], al, b0, b1);
                }
            }
        }
    };

    const int nit = K >> 5;                 // >= 2 for all our GEMMs
    ld_stage(0, 0);  CP_COMMIT();
    ld_stage(1, 32); CP_COMMIT();
    for (int it = 0; it < nit; ++it) {
        CP_WAIT1();
        __syncthreads();
        if (it + 2 < nit) ld_stage((it + 2) % 3, (it + 2) * 32);
        CP_COMMIT();
        compute(it % 3);
    }

    // epilogue
    const int g  = lid >> 2;
    const int tg = lid & 3;
#pragma unroll
    for (int mi = 0; mi < MI; mi++) {
#pragma unroll
        for (int nt = 0; nt < 4; nt++) {
            const int m = bm + wm0 + mi * 16 + g;
            const int n = bn + wn0 + nt * 8 + 2 * tg;
            if (GUARD && n >= Nt) continue;
            float v0 = acc[mi][nt][0], v1 = acc[mi][nt][1];
            float v2 = acc[mi][nt][2], v3 = acc[mi][nt][3];
            if (EPI == 1) {
                const float b0 = bias[n], b1 = bias[n + 1];
                v0 += b0; v1 += b1; v2 += b0; v3 += b1;
                v0 = (v0 > 20.f) ? v0 : log1pf(__expf(v0));
                v1 = (v1 > 20.f) ? v1 : log1pf(__expf(v1));
                v2 = (v2 > 20.f) ? v2 : log1pf(__expf(v2));
                v3 = (v3 > 20.f) ? v3 : log1pf(__expf(v3));
            }
            *(float2*)&C[(size_t)m * ldc + n]       = make_float2(v0, v1);
            *(float2*)&C[(size_t)(m + 8) * ldc + n] = make_float2(v2, v3);
            if (EPI == 2 && n < DTRANK) {
                __half h0 = __float2half_rn(v0), h1 = __float2half_rn(v1);
                __half h2 = __float2half_rn(v2), h3 = __float2half_rn(v3);
                __half l0 = __float2half_rn(v0 - __half2float(h0));
                __half l1 = __float2half_rn(v1 - __half2float(h1));
                __half l2 = __float2half_rn(v2 - __half2float(h2));
                __half l3 = __float2half_rn(v3 - __half2float(h3));
                *(__half2*)&g_dth[(size_t)m * DTRANK + n] = __half2(h0, h1);
                *(__half2*)&g_dtl[(size_t)m * DTRANK + n] = __half2(l0, l1);
                *(__half2*)&g_dth[(size_t)(m + 8) * DTRANK + n] = __half2(h2, h3);
                *(__half2*)&g_dtl[(size_t)(m + 8) * DTRANK + n] = __half2(l2, l3);
            }
        }
    }
}

// ---------------------------------------------------------------------------
// One launch: x -> (hi, lo); W_in/W_x/W_dt/W_out -> hi only.
// ---------------------------------------------------------------------------
#define N0 (BL*DMODEL)
#define N1 (D2*DMODEL)
#define N2 (DBCW*DINNER)
#define N3 (DINNER*DTRANK)
#define N4 (DMODEL*DINNER)
#define NT5 (N0+N1+N2+N3+N4)

__global__ __launch_bounds__(256)
void cvt_split5(const float* __restrict__ s0, const float* __restrict__ s1,
                const float* __restrict__ s2, const float* __restrict__ s3,
                const float* __restrict__ s4)
{
    int idx = blockIdx.x * 256 + threadIdx.x;
    if (idx >= NT5) return;
    if (idx < N0) {
        float v = s0[idx];
        __half h = __float2half_rn(v);
        g_xh[idx] = h;
        g_xl[idx] = __float2half_rn(v - __half2float(h));
        return;
    }
    const float* src; __half* hi; int off;
    if      (idx < N0+N1)       { src = s1; hi = g_winh;  off = idx - N0; }
    else if (idx < N0+N1+N2)    { src = s2; hi = g_wxh;   off = idx - N0-N1; }
    else if (idx < N0+N1+N2+N3) { src = s3; hi = g_wdth;  off = idx - N0-N1-N2; }
    else                        { src = s4; hi = g_wouth; off = idx - N0-N1-N2-N3; }
    hi[off] = __float2half_rn(src[off]);
}

// ---------------------------------------------------------------------------
// Causal depthwise conv (k=4) + bias + SiLU; emits fp32 xc AND split fp16 xc
// ---------------------------------------------------------------------------
__global__ __launch_bounds__(256)
void conv_silu_kernel(const float* __restrict__ conv_w, const float* __restrict__ conv_b)
{
    const size_t idx = (size_t)blockIdx.x * 256 + threadIdx.x;
    if (idx >= (size_t)BL * DINNER) return;
    const int d  = (int)(idx % DINNER);
    const size_t bl = idx / DINNER;
    const int l  = (int)(bl % LENGTH);
    const size_t brow = (bl - l) * (size_t)D2;

    float acc = conv_b[d];
    const float w0 = conv_w[d*4+0], w1 = conv_w[d*4+1];
    const float w2 = conv_w[d*4+2], w3 = conv_w[d*4+3];
    const float* base = g_xz + brow + d;
    if (l >= 3) acc += w0 * base[(size_t)(l-3)*D2];
    if (l >= 2) acc += w1 * base[(size_t)(l-2)*D2];
    if (l >= 1) acc += w2 * base[(size_t)(l-1)*D2];
    acc += w3 * base[(size_t)l*D2];

    float s = acc / (1.f + __expf(-acc));
    g_xc[idx] = s;
    __half h = __float2half_rn(s);
    g_xch[idx] = h;
    g_xcl[idx] = __float2half_rn(s - __half2float(h));
}

// ---------------------------------------------------------------------------
// Selective scan: 8 threads/channel, 2 states each. Lane sub==0 loads the
// shared per-channel scalars (delta, x, z) ONCE and shfl-broadcasts them
// (8x less DRAM than all-lanes loads). Software-pipelined, shuffle-reduced,
// fused D*x skip + silu(z) gate; emits split-fp16 y.
// ---------------------------------------------------------------------------
__global__ __launch_bounds__(128)
void scan_kernel(const float* __restrict__ A_raw, const float* __restrict__ Dvec)
{
    const int tid = threadIdx.x;
    const int sub = tid & 7;
    const int cl  = tid >> 3;
    const int lid = tid & 31;
    const int base = lid & 24;        // lane of sub==0 within this channel
    const int blk = blockIdx.x;
    const int b   = blk >> 7;
    const int c   = ((blk & 127) << 4) + cl;

    const float a0 = -__expf(A_raw[(2*sub+0)*DINNER + c]);
    const float a1 = -__expf(A_raw[(2*sub+1)*DINNER + c]);
    const float Dv = Dvec[c];

    float h0 = 0.f, h1 = 0.f;

    const float* dptr = g_delta + (size_t)b*LENGTH*DINNER + c;
    const float* xptr = g_xc    + (size_t)b*LENGTH*DINNER + c;
    const float* bcp  = g_dbc   + (size_t)b*LENGTH*DBCW + DTRANK + 2*sub;
    const float* zptr = g_xz    + (size_t)b*LENGTH*D2 + DINNER + c;
    __half* yhp = g_yh + (size_t)b*LENGTH*DINNER + c;
    __half* ylp = g_yl + (size_t)b*LENGTH*DINNER + c;

    // preload t=0 (sub0 loads, broadcast)
    float d_c = 0.f, x_c = 0.f, z_c = 0.f;
    if (sub == 0) { d_c = *dptr; x_c = *xptr; z_c = *zptr; }
    d_c = __shfl_sync(0xffffffffu, d_c, base);
    x_c = __shfl_sync(0xffffffffu, x_c, base);
    float2 B_c = *(const float2*)bcp;
    float2 C_c = *(const float2*)(bcp + DSTATE);

    for (int t = 0; t < LENGTH; ++t) {
        // prefetch t+1 (sub0 only; broadcast at end of iteration)
        float d_n = 0.f, x_n = 0.f, z_n = 0.f;
        float2 B_n = make_float2(0.f, 0.f), C_n = make_float2(0.f, 0.f);
        if (t + 1 < LENGTH) {
            if (sub == 0) {
                d_n = dptr[DINNER];
                x_n = xptr[DINNER];
                z_n = zptr[D2];
            }
            B_n = *(const float2*)(bcp + DBCW);
            C_n = *(const float2*)(bcp + DBCW + DSTATE);
        }

        const float dx = d_c * x_c;
        h0 = fmaf(__expf(d_c * a0), h0, B_c.x * dx);
        h1 = fmaf(__expf(d_c * a1), h1, B_c.y * dx);

        float acc = C_c.x * h0 + C_c.y * h1;
        acc += __shfl_xor_sync(0xffffffffu, acc, 1);
        acc += __shfl_xor_sync(0xffffffffu, acc, 2);
        acc += __shfl_xor_sync(0xffffffffu, acc, 4);

        if (sub == 0) {
            float y = (acc + Dv * x_c) * (z_c / (1.f + __expf(-z_c)));
            __half h = __float2half_rn(y);
            *yhp = h;
            *ylp = __float2half_rn(y - __half2float(h));
        }

        d_c = __shfl_sync(0xffffffffu, d_n, base);
        x_c = __shfl_sync(0xffffffffu, x_n, base);
        z_c = z_n;
        B_c = B_n; C_c = C_n;
        dptr += DINNER; xptr += DINNER; bcp += DBCW; zptr += D2;
        yhp += DINNER; ylp += DINNER;
    }
}

// ---------------------------------------------------------------------------
extern "C" void kernel_launch(void* const* d_in, const int* in_sizes, int n_in,
                              void* d_out, int out_size)
{
    const float* x      = (const float*)d_in[0];
    const float* W_in   = (const float*)d_in[1];
    const float* conv_w = (const float*)d_in[2];
    const float* conv_b = (const float*)d_in[3];
    const float* W_x    = (const float*)d_in[4];
    const float* W_dt   = (const float*)d_in[5];
    const float* b_dt   = (const float*)d_in[6];
    const float* A_raw  = (const float*)d_in[7];
    const float* Dvec   = (const float*)d_in[8];
    const float* W_out  = (const float*)d_in[9];
    float* out = (float*)d_out;

    float *p_xz, *p_dbc, *p_delta;
    __half *p_xh,*p_xl,*p_winh,*p_xch,*p_xcl,*p_wxh;
    __half *p_dth,*p_dtl,*p_wdth,*p_yh,*p_yl,*p_wouth;
    cudaGetSymbolAddress((void**)&p_xz,    g_xz);
    cudaGetSymbolAddress((void**)&p_dbc,   g_dbc);
    cudaGetSymbolAddress((void**)&p_delta, g_delta);
    cudaGetSymbolAddress((void**)&p_xh,    g_xh);
    cudaGetSymbolAddress((void**)&p_xl,    g_xl);
    cudaGetSymbolAddress((void**)&p_winh,  g_winh);
    cudaGetSymbolAddress((void**)&p_xch,   g_xch);
    cudaGetSymbolAddress((void**)&p_xcl,   g_xcl);
    cudaGetSymbolAddress((void**)&p_wxh,   g_wxh);
    cudaGetSymbolAddress((void**)&p_dth,   g_dth);
    cudaGetSymbolAddress((void**)&p_dtl,   g_dtl);
    cudaGetSymbolAddress((void**)&p_wdth,  g_wdth);
    cudaGetSymbolAddress((void**)&p_yh,    g_yh);
    cudaGetSymbolAddress((void**)&p_yl,    g_yl);
    cudaGetSymbolAddress((void**)&p_wouth, g_wouth);

    const int SMEM128 = 3 * (2*128*80 + 128*80);   // 92160
    const int SMEM64  = 3 * (2*64*80  + 128*80);   // 61440
    cudaFuncSetAttribute(tgemm<128,0,false>, cudaFuncAttributeMaxDynamicSharedMemorySize, SMEM128);
    cudaFuncSetAttribute(tgemm< 64,2,true >, cudaFuncAttributeMaxDynamicSharedMemorySize, SMEM64);
    cudaFuncSetAttribute(tgemm<128,1,false>, cudaFuncAttributeMaxDynamicSharedMemorySize, SMEM128);

    // 0) all input/weight conversions in one launch
    cvt_split5<<<(NT5 + 255)/256, 256>>>(x, W_in, W_x, W_dt, W_out);

    // 1) xz = x @ W_in^T   (8192 x 4096, K=1024), 2-pass
    tgemm<128,0,false><<<dim3(D2/128, BL/128), 256, SMEM128>>>(
        p_xh, p_xl, DMODEL, p_winh, DMODEL, p_xz, D2, D2, DMODEL, nullptr);

    // 2) conv + silu (emits fp32 + split fp16 xc)
    conv_silu_kernel<<<(unsigned)(((size_t)BL*DINNER + 255)/256), 256>>>(conv_w, conv_b);

    // 3) dbc = xc @ W_x^T  (8192 x 96, K=2048), MTILE=64 -> grid 128, fused dt split
    tgemm<64,2,true><<<dim3(1, BL/64), 256, SMEM64>>>(
        p_xch, p_xcl, DINNER, p_wxh, DINNER, p_dbc, DBCW, DBCW, DINNER, nullptr);

    // 4) delta = softplus(dt @ W_dt^T + b_dt)  (8192 x 2048, K=64), 2-pass
    tgemm<128,1,false><<<dim3(DINNER/128, BL/128), 256, SMEM128>>>(
        p_dth, p_dtl, DTRANK, p_wdth, DTRANK, p_delta, DINNER, DINNER, DTRANK, b_dt);

    // 5) selective scan + gate -> split fp16 y
    scan_kernel<<<BATCH*128, 128>>>(A_raw, Dvec);

    // 6) out = y @ W_out^T (8192 x 1024, K=2048), 2-pass
    tgemm<128,0,false><<<dim3(DMODEL/128, BL/128), 256, SMEM128>>>(
        p_yh, p_yl, DINNER, p_wouth, DINNER, out, DMODEL, DMODEL, DINNER, nullptr);
}

// round 11
// speedup vs baseline: 4.2334x; 1.5430x over previous
#include <cuda_runtime.h>
#include <cuda_fp16.h>
#include <cstdint>

// Problem dims (fixed)
#define BATCH   4
#define LENGTH  2048
#define DMODEL  1024
#define DINNER  2048
#define DSTATE  16
#define DTRANK  64
#define BL      (BATCH*LENGTH)        // 8192
#define D2      (2*DINNER)            // 4096
#define DBCW    (DTRANK + 2*DSTATE)   // 96

// ------------------- static scratch (no cudaMalloc allowed) -------------------
__device__ float g_xz[(size_t)BL * D2];
__device__ float g_xc[(size_t)BL * DINNER];
__device__ float g_dbc[(size_t)BL * DBCW];
__device__ float g_delta[(size_t)BL * DINNER];

__device__ __half g_xh  [(size_t)BL*DMODEL],   g_xl  [(size_t)BL*DMODEL];
__device__ __half g_winh[(size_t)D2*DMODEL];
__device__ __half g_xch [(size_t)BL*DINNER],   g_xcl [(size_t)BL*DINNER];
__device__ __half g_wxh [(size_t)DBCW*DINNER];
__device__ __half g_dth [(size_t)BL*DTRANK],   g_dtl [(size_t)BL*DTRANK];
__device__ __half g_wdth[(size_t)DINNER*DTRANK];
__device__ __half g_yh  [(size_t)BL*DINNER],   g_yl  [(size_t)BL*DINNER];
__device__ __half g_wouth[(size_t)DMODEL*DINNER];

// ------------------------------ PTX helpers ------------------------------
__device__ __forceinline__ uint32_t s2u(const void* p) {
    uint32_t a;
    asm("{ .reg .u64 t; cvta.to.shared.u64 t, %1; cvt.u32.u64 %0, t; }" : "=r"(a) : "l"(p));
    return a;
}
#define CP16(d, g) \
    asm volatile("cp.async.cg.shared.global [%0], [%1], 16;" :: "r"(d), "l"(g))
#define CP16Z(d, g, v) \
    asm volatile("cp.async.cg.shared.global [%0], [%1], 16, %2;" :: "r"(d), "l"(g), "r"(v))
#define CP_COMMIT() asm volatile("cp.async.commit_group;" ::: "memory")
#define CP_WAIT1()  asm volatile("cp.async.wait_group 1;" ::: "memory")

#define LDSM4(r, a) \
    asm volatile("ldmatrix.sync.aligned.m8n8.x4.shared.b16 {%0,%1,%2,%3}, [%4];" \
        : "=r"((r)[0]), "=r"((r)[1]), "=r"((r)[2]), "=r"((r)[3]) : "r"(a))

#define MMA16816(c, a, b0, b1) \
    asm volatile("mma.sync.aligned.m16n8k16.row.col.f32.f16.f16.f32 " \
        "{%0,%1,%2,%3}, {%4,%5,%6,%7}, {%8,%9}, {%0,%1,%2,%3};" \
        : "+f"((c)[0]), "+f"((c)[1]), "+f"((c)[2]), "+f"((c)[3]) \
        : "r"((a)[0]), "r"((a)[1]), "r"((a)[2]), "r"((a)[3]), "r"(b0), "r"(b1))

// ---------------------------------------------------------------------------
// 2-pass split-fp16 warp-MMA GEMM (unchanged from the passing R10 kernel).
// ---------------------------------------------------------------------------
template<int MTILE, int EPI, bool GUARD>
__global__ __launch_bounds__(256, 2)
void tgemm(const __half* __restrict__ Ah, const __half* __restrict__ Al, int lda,
           const __half* __restrict__ Bh, int ldb,
           float* __restrict__ C, int ldc, int Nt, int K,
           const float* __restrict__ bias)
{
    constexpr uint32_t OFF_AL = (uint32_t)MTILE * 80u;
    constexpr uint32_t OFF_B  = 2u * (uint32_t)MTILE * 80u;
    constexpr uint32_t STG    = OFF_B + 128u * 80u;
    constexpr int MI = MTILE / 32;

    extern __shared__ char smem[];
    const uint32_t sb = s2u(smem);

    const int tid = threadIdx.x;
    const int lid = tid & 31;
    const int wid = tid >> 5;
    const int wm0 = (wid & 1) * (MTILE / 2);
    const int wn0 = (wid >> 1) * 32;

    const int bm = blockIdx.y * MTILE;
    const int bn = blockIdx.x * 128;

    float acc[MI][4][4];
#pragma unroll
    for (int i = 0; i < MI; i++)
#pragma unroll
        for (int j = 0; j < 4; j++)
#pragma unroll
            for (int k = 0; k < 4; k++) acc[i][j][k] = 0.f;

    auto ld_stage = [&](int s, int kc) {
        const uint32_t base = sb + (uint32_t)s * STG;
        const __half* pAh = Ah + (size_t)bm * lda + kc;
        const __half* pAl = Al + (size_t)bm * lda + kc;
        const __half* pBh = Bh + (size_t)bn * ldb + kc;
#pragma unroll
        for (int i = 0; i < (MTILE * 4) / 256; ++i) {
            const int c   = tid + i * 256;
            const int row = c >> 2;
            const int ch  = (c & 3) * 16;
            const uint32_t o = (uint32_t)row * 80u + (uint32_t)ch;
            CP16(base + o,          (const char*)(pAh + (size_t)row * lda) + ch);
            CP16(base + OFF_AL + o, (const char*)(pAl + (size_t)row * lda) + ch);
        }
#pragma unroll
        for (int i = 0; i < 2; ++i) {
            const int c   = tid + i * 256;
            const int row = c >> 2;
            const int ch  = (c & 3) * 16;
            const uint32_t o = (uint32_t)row * 80u + (uint32_t)ch;
            if (!GUARD) {
                CP16(base + OFF_B + o, (const char*)(pBh + (size_t)row * ldb) + ch);
            } else {
                const uint32_t v = ((bn + row) < Nt) ? 16u : 0u;
                CP16Z(base + OFF_B + o, (const char*)(pBh + (size_t)row * ldb) + ch, v);
            }
        }
    };

    const uint32_t arow  = (uint32_t)(wm0 + (lid & 15));
    const uint32_t akoff = (uint32_t)((lid >> 4) << 3);
    const uint32_t brow  = (uint32_t)(wn0 + ((lid >> 4) << 3) + (lid & 7));
    const uint32_t bkoff = (uint32_t)(((lid >> 3) & 1) << 3);

    auto compute = [&](int s) {
        const uint32_t aB = sb + (uint32_t)s * STG;
        const uint32_t bB = aB + OFF_B;
#pragma unroll
        for (int kk = 0; kk < 2; ++kk) {
            uint32_t bh[2][4];
#pragma unroll
            for (int bi = 0; bi < 2; bi++) {
                const uint32_t bd = bB + (brow + bi*16) * 80u + (bkoff + kk*16) * 2u;
                LDSM4(bh[bi], bd);
            }
#pragma unroll
            for (int mi = 0; mi < MI; mi++) {
                uint32_t ah[4], al[4];
                const uint32_t ad = aB + (arow + mi*16) * 80u + (akoff + kk*16) * 2u;
                LDSM4(ah, ad);
                LDSM4(al, ad + OFF_AL);
#pragma unroll
                for (int nt = 0; nt < 4; nt++) {
                    const uint32_t b0 = bh[nt>>1][(nt&1)*2], b1 = bh[nt>>1][(nt&1)*2+1];
                    MMA16816(acc[mi][nt], ah, b0, b1);
                    MMA16816(acc[mi][nt], al, b0, b1);
                }
            }
        }
    };

    const int nit = K >> 5;
    ld_stage(0, 0);  CP_COMMIT();
    ld_stage(1, 32); CP_COMMIT();
    for (int it = 0; it < nit; ++it) {
        CP_WAIT1();
        __syncthreads();
        if (it + 2 < nit) ld_stage((it + 2) % 3, (it + 2) * 32);
        CP_COMMIT();
        compute(it % 3);
    }

    const int g  = lid >> 2;
    const int tg = lid & 3;
#pragma unroll
    for (int mi = 0; mi < MI; mi++) {
#pragma unroll
        for (int nt = 0; nt < 4; nt++) {
            const int m = bm + wm0 + mi * 16 + g;
            const int n = bn + wn0 + nt * 8 + 2 * tg;
            if (GUARD && n >= Nt) continue;
            float v0 = acc[mi][nt][0], v1 = acc[mi][nt][1];
            float v2 = acc[mi][nt][2], v3 = acc[mi][nt][3];
            if (EPI == 1) {
                const float b0 = bias[n], b1 = bias[n + 1];
                v0 += b0; v1 += b1; v2 += b0; v3 += b1;
                v0 = (v0 > 20.f) ? v0 : log1pf(__expf(v0));
                v1 = (v1 > 20.f) ? v1 : log1pf(__expf(v1));
                v2 = (v2 > 20.f) ? v2 : log1pf(__expf(v2));
                v3 = (v3 > 20.f) ? v3 : log1pf(__expf(v3));
            }
            *(float2*)&C[(size_t)m * ldc + n]       = make_float2(v0, v1);
            *(float2*)&C[(size_t)(m + 8) * ldc + n] = make_float2(v2, v3);
            if (EPI == 2 && n < DTRANK) {
                __half h0 = __float2half_rn(v0), h1 = __float2half_rn(v1);
                __half h2 = __float2half_rn(v2), h3 = __float2half_rn(v3);
                __half l0 = __float2half_rn(v0 - __half2float(h0));
                __half l1 = __float2half_rn(v1 - __half2float(h1));
                __half l2 = __float2half_rn(v2 - __half2float(h2));
                __half l3 = __float2half_rn(v3 - __half2float(h3));
                *(__half2*)&g_dth[(size_t)m * DTRANK + n] = __half2(h0, h1);
                *(__half2*)&g_dtl[(size_t)m * DTRANK + n] = __half2(l0, l1);
                *(__half2*)&g_dth[(size_t)(m + 8) * DTRANK + n] = __half2(h2, h3);
                *(__half2*)&g_dtl[(size_t)(m + 8) * DTRANK + n] = __half2(l2, l3);
            }
        }
    }
}

// ---------------------------------------------------------------------------
// One launch: x -> (hi, lo); W_in/W_x/W_dt/W_out -> hi only.
// ---------------------------------------------------------------------------
#define N0 (BL*DMODEL)
#define N1 (D2*DMODEL)
#define N2 (DBCW*DINNER)
#define N3 (DINNER*DTRANK)
#define N4 (DMODEL*DINNER)
#define NT5 (N0+N1+N2+N3+N4)

__global__ __launch_bounds__(256)
void cvt_split5(const float* __restrict__ s0, const float* __restrict__ s1,
                const float* __restrict__ s2, const float* __restrict__ s3,
                const float* __restrict__ s4)
{
    int idx = blockIdx.x * 256 + threadIdx.x;
    if (idx >= NT5) return;
    if (idx < N0) {
        float v = s0[idx];
        __half h = __float2half_rn(v);
        g_xh[idx] = h;
        g_xl[idx] = __float2half_rn(v - __half2float(h));
        return;
    }
    const float* src; __half* hi; int off;
    if      (idx < N0+N1)       { src = s1; hi = g_winh;  off = idx - N0; }
    else if (idx < N0+N1+N2)    { src = s2; hi = g_wxh;   off = idx - N0-N1; }
    else if (idx < N0+N1+N2+N3) { src = s3; hi = g_wdth;  off = idx - N0-N1-N2; }
    else                        { src = s4; hi = g_wouth; off = idx - N0-N1-N2-N3; }
    hi[off] = __float2half_rn(src[off]);
}

// ---------------------------------------------------------------------------
// Causal depthwise conv (k=4) + bias + SiLU; emits fp32 xc AND split fp16 xc
// ---------------------------------------------------------------------------
__global__ __launch_bounds__(256)
void conv_silu_kernel(const float* __restrict__ conv_w, const float* __restrict__ conv_b)
{
    const size_t idx = (size_t)blockIdx.x * 256 + threadIdx.x;
    if (idx >= (size_t)BL * DINNER) return;
    const int d  = (int)(idx % DINNER);
    const size_t bl = idx / DINNER;
    const int l  = (int)(bl % LENGTH);
    const size_t brow = (bl - l) * (size_t)D2;

    float acc = conv_b[d];
    const float w0 = conv_w[d*4+0], w1 = conv_w[d*4+1];
    const float w2 = conv_w[d*4+2], w3 = conv_w[d*4+3];
    const float* base = g_xz + brow + d;
    if (l >= 3) acc += w0 * base[(size_t)(l-3)*D2];
    if (l >= 2) acc += w1 * base[(size_t)(l-2)*D2];
    if (l >= 1) acc += w2 * base[(size_t)(l-1)*D2];
    acc += w3 * base[(size_t)l*D2];

    float s = acc / (1.f + __expf(-acc));
    g_xc[idx] = s;
    __half h = __float2half_rn(s);
    g_xch[idx] = h;
    g_xcl[idx] = __float2half_rn(s - __half2float(h));
}

// ---------------------------------------------------------------------------
// Selective scan v2: windowed cp.async staging.
// Block = 128 threads = 16 channels x 8 state-threads, one batch b.
// Window = 16 timesteps. Per window, cooperatively cp.async:
//   delta[16t][16c], xc[16t][16c], z[16t][16c]  (1KB each)
//   dbc B|C rows [16t][32]                      (2KB, shared by all channels)
// into a double-buffered smem stage; inner 16 steps touch only smem.
// ---------------------------------------------------------------------------
#define SW 16     // window timesteps
__global__ __launch_bounds__(128)
void scan_kernel(const float* __restrict__ A_raw, const float* __restrict__ Dvec)
{
    __shared__ __align__(16) float s_d [2][SW][16];
    __shared__ __align__(16) float s_x [2][SW][16];
    __shared__ __align__(16) float s_z [2][SW][16];
    __shared__ __align__(16) float s_bc[2][SW][32];

    const int tid = threadIdx.x;
    const int sub = tid & 7;          // state pair 0..7
    const int ch  = tid >> 3;         // channel 0..15
    const int blk = blockIdx.x;
    const int b   = blk >> 7;
    const int c0  = (blk & 127) << 4;
    const int c   = c0 + ch;

    const float a0 = -__expf(A_raw[(2*sub+0)*DINNER + c]);
    const float a1 = -__expf(A_raw[(2*sub+1)*DINNER + c]);
    const float Dv = Dvec[c];

    const float* dbase  = g_delta + (size_t)b*LENGTH*DINNER + c0;
    const float* xbase  = g_xc    + (size_t)b*LENGTH*DINNER + c0;
    const float* zbase  = g_xz    + (size_t)b*LENGTH*D2 + DINNER + c0;
    const float* bcbase = g_dbc   + (size_t)b*LENGTH*DBCW + DTRANK;
    __half* yhp = g_yh + (size_t)b*LENGTH*DINNER + c;
    __half* ylp = g_yl + (size_t)b*LENGTH*DINNER + c;

    // cooperative window loader: one cp.async 16B each for d/x/z (64 threads
    // per array), one for bc (all 128 threads).
    auto ld_win = [&](int s, int t0) {
        const int ttA = tid >> 2, qA = (tid & 3) * 4;      // threads 0..63 view
        if (tid < 64) {
            CP16(s2u(&s_d[s][ttA][qA]), dbase + (size_t)(t0 + ttA)*DINNER + qA);
            CP16(s2u(&s_z[s][ttA][qA]), zbase + (size_t)(t0 + ttA)*D2 + qA);
        } else {
            const int tt = (tid - 64) >> 2, q = ((tid - 64) & 3) * 4;
            CP16(s2u(&s_x[s][tt][q]), xbase + (size_t)(t0 + tt)*DINNER + q);
        }
        const int ttB = tid >> 3, qB = (tid & 7) * 4;      // all 128 threads
        CP16(s2u(&s_bc[s][ttB][qB]), bcbase + (size_t)(t0 + ttB)*DBCW + qB);
    };

    float h0 = 0.f, h1 = 0.f;
    const int NW = LENGTH / SW;       // 128 windows

    ld_win(0, 0);    CP_COMMIT();
    ld_win(1, SW);   CP_COMMIT();

    for (int w = 0; w < NW; ++w) {
        CP_WAIT1();
        __syncthreads();
        const int buf = w & 1;
        const int t0  = w * SW;

#pragma unroll
        for (int tt = 0; tt < SW; ++tt) {
            const float d  = s_d[buf][tt][ch];
            const float xv = s_x[buf][tt][ch];
            const float2 Bv = *(const float2*)&s_bc[buf][tt][2*sub];
            const float2 Cv = *(const float2*)&s_bc[buf][tt][16 + 2*sub];
            const float dx = d * xv;

            h0 = fmaf(__expf(d * a0), h0, Bv.x * dx);
            h1 = fmaf(__expf(d * a1), h1, Bv.y * dx);

            float acc = Cv.x * h0 + Cv.y * h1;
            acc += __shfl_xor_sync(0xffffffffu, acc, 1);
            acc += __shfl_xor_sync(0xffffffffu, acc, 2);
            acc += __shfl_xor_sync(0xffffffffu, acc, 4);

            if (sub == 0) {
                const float z = s_z[buf][tt][ch];
                float y = (acc + Dv * xv) * (z / (1.f + __expf(-z)));
                __half h = __float2half_rn(y);
                yhp[(size_t)(t0 + tt) * DINNER] = h;
                ylp[(size_t)(t0 + tt) * DINNER] = __float2half_rn(y - __half2float(h));
            }
        }

        __syncthreads();                       // done reading buf before refill
        if (w + 2 < NW) ld_win(buf, (w + 2) * SW);
        CP_COMMIT();
    }
}

// ---------------------------------------------------------------------------
extern "C" void kernel_launch(void* const* d_in, const int* in_sizes, int n_in,
                              void* d_out, int out_size)
{
    const float* x      = (const float*)d_in[0];
    const float* W_in   = (const float*)d_in[1];
    const float* conv_w = (const float*)d_in[2];
    const float* conv_b = (const float*)d_in[3];
    const float* W_x    = (const float*)d_in[4];
    const float* W_dt   = (const float*)d_in[5];
    const float* b_dt   = (const float*)d_in[6];
    const float* A_raw  = (const float*)d_in[7];
    const float* Dvec   = (const float*)d_in[8];
    const float* W_out  = (const float*)d_in[9];
    float* out = (float*)d_out;

    float *p_xz, *p_dbc, *p_delta;
    __half *p_xh,*p_xl,*p_winh,*p_xch,*p_xcl,*p_wxh;
    __half *p_dth,*p_dtl,*p_wdth,*p_yh,*p_yl,*p_wouth;
    cudaGetSymbolAddress((void**)&p_xz,    g_xz);
    cudaGetSymbolAddress((void**)&p_dbc,   g_dbc);
    cudaGetSymbolAddress((void**)&p_delta, g_delta);
    cudaGetSymbolAddress((void**)&p_xh,    g_xh);
    cudaGetSymbolAddress((void**)&p_xl,    g_xl);
    cudaGetSymbolAddress((void**)&p_winh,  g_winh);
    cudaGetSymbolAddress((void**)&p_xch,   g_xch);
    cudaGetSymbolAddress((void**)&p_xcl,   g_xcl);
    cudaGetSymbolAddress((void**)&p_wxh,   g_wxh);
    cudaGetSymbolAddress((void**)&p_dth,   g_dth);
    cudaGetSymbolAddress((void**)&p_dtl,   g_dtl);
    cudaGetSymbolAddress((void**)&p_wdth,  g_wdth);
    cudaGetSymbolAddress((void**)&p_yh,    g_yh);
    cudaGetSymbolAddress((void**)&p_yl,    g_yl);
    cudaGetSymbolAddress((void**)&p_wouth, g_wouth);

    const int SMEM128 = 3 * (2*128*80 + 128*80);   // 92160
    const int SMEM64  = 3 * (2*64*80  + 128*80);   // 61440
    cudaFuncSetAttribute(tgemm<128,0,false>, cudaFuncAttributeMaxDynamicSharedMemorySize, SMEM128);
    cudaFuncSetAttribute(tgemm< 64,2,true >, cudaFuncAttributeMaxDynamicSharedMemorySize, SMEM64);
    cudaFuncSetAttribute(tgemm<128,1,false>, cudaFuncAttributeMaxDynamicSharedMemorySize, SMEM128);

    // 0) all input/weight conversions in one launch
    cvt_split5<<<(NT5 + 255)/256, 256>>>(x, W_in, W_x, W_dt, W_out);

    // 1) xz = x @ W_in^T   (8192 x 4096, K=1024), 2-pass
    tgemm<128,0,false><<<dim3(D2/128, BL/128), 256, SMEM128>>>(
        p_xh, p_xl, DMODEL, p_winh, DMODEL, p_xz, D2, D2, DMODEL, nullptr);

    // 2) conv + silu (emits fp32 + split fp16 xc)
    conv_silu_kernel<<<(unsigned)(((size_t)BL*DINNER + 255)/256), 256>>>(conv_w, conv_b);

    // 3) dbc = xc @ W_x^T  (8192 x 96, K=2048), MTILE=64, fused dt split
    tgemm<64,2,true><<<dim3(1, BL/64), 256, SMEM64>>>(
        p_xch, p_xcl, DINNER, p_wxh, DINNER, p_dbc, DBCW, DBCW, DINNER, nullptr);

    // 4) delta = softplus(dt @ W_dt^T + b_dt)  (8192 x 2048, K=64), 2-pass
    tgemm<128,1,false><<<dim3(DINNER/128, BL/128), 256, SMEM128>>>(
        p_dth, p_dtl, DTRANK, p_wdth, DTRANK, p_delta, DINNER, DINNER, DTRANK, b_dt);

    // 5) selective scan v2 (windowed cp.async staging) -> split fp16 y
    scan_kernel<<<BATCH*128, 128>>>(A_raw, Dvec);

    // 6) out = y @ W_out^T (8192 x 1024, K=2048), 2-pass
    tgemm<128,0,false><<<dim3(DMODEL/128, BL/128), 256, SMEM128>>>(
        p_yh, p_yl, DINNER, p_wouth, DINNER, out, DMODEL, DMODEL, DINNER, nullptr);
}

// round 13
// speedup vs baseline: 5.5576x; 1.3128x over previous
#include <cuda_runtime.h>
#include <cuda_fp16.h>
#include <cstdint>

// Problem dims (fixed)
#define BATCH   4
#define LENGTH  2048
#define DMODEL  1024
#define DINNER  2048
#define DSTATE  16
#define DTRANK  64
#define BL      (BATCH*LENGTH)        // 8192
#define D2      (2*DINNER)            // 4096
#define DBCW    (DTRANK + 2*DSTATE)   // 96

// ------------------- static scratch (no cudaMalloc allowed) -------------------
__device__ float g_xz[(size_t)BL * D2];
__device__ float g_xc[(size_t)BL * DINNER];
__device__ float g_dbc[(size_t)BL * DBCW];
__device__ float g_delta[(size_t)BL * DINNER];

__device__ __half g_xh  [(size_t)BL*DMODEL];
__device__ __half g_winh[(size_t)D2*DMODEL];
__device__ __half g_xch [(size_t)BL*DINNER],   g_xcl [(size_t)BL*DINNER];
__device__ __half g_wxh [(size_t)DBCW*DINNER];
__device__ __half g_dth [(size_t)BL*DTRANK],   g_dtl [(size_t)BL*DTRANK];
__device__ __half g_wdth[(size_t)DINNER*DTRANK];
__device__ __half g_yh  [(size_t)BL*DINNER];
__device__ __half g_wouth[(size_t)DMODEL*DINNER];

// ------------------------------ PTX helpers ------------------------------
__device__ __forceinline__ uint32_t s2u(const void* p) {
    uint32_t a;
    asm("{ .reg .u64 t; cvta.to.shared.u64 t, %1; cvt.u32.u64 %0, t; }" : "=r"(a) : "l"(p));
    return a;
}
#define CP16(d, g) \
    asm volatile("cp.async.cg.shared.global [%0], [%1], 16;" :: "r"(d), "l"(g))
#define CP16Z(d, g, v) \
    asm volatile("cp.async.cg.shared.global [%0], [%1], 16, %2;" :: "r"(d), "l"(g), "r"(v))
#define CP_COMMIT() asm volatile("cp.async.commit_group;" ::: "memory")
#define CP_WAIT1()  asm volatile("cp.async.wait_group 1;" ::: "memory")

#define LDSM4(r, a) \
    asm volatile("ldmatrix.sync.aligned.m8n8.x4.shared.b16 {%0,%1,%2,%3}, [%4];" \
        : "=r"((r)[0]), "=r"((r)[1]), "=r"((r)[2]), "=r"((r)[3]) : "r"(a))

#define MMA16816(c, a, b0, b1) \
    asm volatile("mma.sync.aligned.m16n8k16.row.col.f32.f16.f16.f32 " \
        "{%0,%1,%2,%3}, {%4,%5,%6,%7}, {%8,%9}, {%0,%1,%2,%3};" \
        : "+f"((c)[0]), "+f"((c)[1]), "+f"((c)[2]), "+f"((c)[3]) \
        : "r"((a)[0]), "r"((a)[1]), "r"((a)[2]), "r"((a)[3]), "r"(b0), "r"(b1))

// ---------------------------------------------------------------------------
// Split-fp16 warp-MMA GEMM: C[m][n] = sum_k A[m][k]*B[n][k] (fp32 out)
// PASSES=2: A split (Ah+Al)·Bh.  PASSES=1: single Ah·Bh.
// CTA tile MTILE x 128, BK=32, 256 threads (2x4 warps), 3-stage cp.async
// pipeline (wait_group 1), 80B-padded smem rows, 2 CTAs/SM.
// EPI: 0 plain, 1 softplus(v+bias[n]), 2 plain + fused fp16 dt-split (n<64).
// GUARD: bounds-check B rows / C cols against Nt.
// ---------------------------------------------------------------------------
template<int MTILE, int PASSES, int EPI, bool GUARD>
__global__ __launch_bounds__(256, 2)
void tgemm(const __half* __restrict__ Ah, const __half* __restrict__ Al, int lda,
           const __half* __restrict__ Bh, int ldb,
           float* __restrict__ C, int ldc, int Nt, int K,
           const float* __restrict__ bias)
{
    constexpr uint32_t OFF_AL = (uint32_t)MTILE * 80u;                 // valid if PASSES==2
    constexpr uint32_t OFF_B  = (uint32_t)PASSES * (uint32_t)MTILE * 80u;
    constexpr uint32_t STG    = OFF_B + 128u * 80u;
    constexpr int MI = MTILE / 32;

    extern __shared__ char smem[];
    const uint32_t sb = s2u(smem);

    const int tid = threadIdx.x;
    const int lid = tid & 31;
    const int wid = tid >> 5;
    const int wm0 = (wid & 1) * (MTILE / 2);
    const int wn0 = (wid >> 1) * 32;

    const int bm = blockIdx.y * MTILE;
    const int bn = blockIdx.x * 128;

    float acc[MI][4][4];
#pragma unroll
    for (int i = 0; i < MI; i++)
#pragma unroll
        for (int j = 0; j < 4; j++)
#pragma unroll
            for (int k = 0; k < 4; k++) acc[i][j][k] = 0.f;

    auto ld_stage = [&](int s, int kc) {
        const uint32_t base = sb + (uint32_t)s * STG;
        const __half* pAh = Ah + (size_t)bm * lda + kc;
        const __half* pAl = (PASSES == 2) ? (Al + (size_t)bm * lda + kc) : pAh;
        const __half* pBh = Bh + (size_t)bn * ldb + kc;
#pragma unroll
        for (int i = 0; i < (MTILE * 4) / 256; ++i) {
            const int c   = tid + i * 256;
            const int row = c >> 2;
            const int ch  = (c & 3) * 16;
            const uint32_t o = (uint32_t)row * 80u + (uint32_t)ch;
            CP16(base + o, (const char*)(pAh + (size_t)row * lda) + ch);
            if (PASSES == 2)
                CP16(base + OFF_AL + o, (const char*)(pAl + (size_t)row * lda) + ch);
        }
#pragma unroll
        for (int i = 0; i < 2; ++i) {
            const int c   = tid + i * 256;
            const int row = c >> 2;
            const int ch  = (c & 3) * 16;
            const uint32_t o = (uint32_t)row * 80u + (uint32_t)ch;
            if (!GUARD) {
                CP16(base + OFF_B + o, (const char*)(pBh + (size_t)row * ldb) + ch);
            } else {
                const uint32_t v = ((bn + row) < Nt) ? 16u : 0u;
                CP16Z(base + OFF_B + o, (const char*)(pBh + (size_t)row * ldb) + ch, v);
            }
        }
    };

    const uint32_t arow  = (uint32_t)(wm0 + (lid & 15));
    const uint32_t akoff = (uint32_t)((lid >> 4) << 3);
    const uint32_t brow  = (uint32_t)(wn0 + ((lid >> 4) << 3) + (lid & 7));
    const uint32_t bkoff = (uint32_t)(((lid >> 3) & 1) << 3);

    auto compute = [&](int s) {
        const uint32_t aB = sb + (uint32_t)s * STG;
        const uint32_t bB = aB + OFF_B;
#pragma unroll
        for (int kk = 0; kk < 2; ++kk) {
            uint32_t bh[2][4];
#pragma unroll
            for (int bi = 0; bi < 2; bi++) {
                const uint32_t bd = bB + (brow + bi*16) * 80u + (bkoff + kk*16) * 2u;
                LDSM4(bh[bi], bd);
            }
#pragma unroll
            for (int mi = 0; mi < MI; mi++) {
                uint32_t ah[4], al[4];
                const uint32_t ad = aB + (arow + mi*16) * 80u + (akoff + kk*16) * 2u;
                LDSM4(ah, ad);
                if (PASSES == 2) LDSM4(al, ad + OFF_AL);
#pragma unroll
                for (int nt = 0; nt < 4; nt++) {
                    const uint32_t b0 = bh[nt>>1][(nt&1)*2], b1 = bh[nt>>1][(nt&1)*2+1];
                    MMA16816(acc[mi][nt], ah, b0, b1);
                    if (PASSES == 2) MMA16816(acc[mi][nt], al, b0, b1);
                }
            }
        }
    };

    const int nit = K >> 5;
    ld_stage(0, 0);  CP_COMMIT();
    ld_stage(1, 32); CP_COMMIT();
    for (int it = 0; it < nit; ++it) {
        CP_WAIT1();
        __syncthreads();
        if (it + 2 < nit) ld_stage((it + 2) % 3, (it + 2) * 32);
        CP_COMMIT();
        compute(it % 3);
    }

    const int g  = lid >> 2;
    const int tg = lid & 3;
#pragma unroll
    for (int mi = 0; mi < MI; mi++) {
#pragma unroll
        for (int nt = 0; nt < 4; nt++) {
            const int m = bm + wm0 + mi * 16 + g;
            const int n = bn + wn0 + nt * 8 + 2 * tg;
            if (GUARD && n >= Nt) continue;
            float v0 = acc[mi][nt][0], v1 = acc[mi][nt][1];
            float v2 = acc[mi][nt][2], v3 = acc[mi][nt][3];
            if (EPI == 1) {
                const float b0 = bias[n], b1 = bias[n + 1];
                v0 += b0; v1 += b1; v2 += b0; v3 += b1;
                v0 = (v0 > 20.f) ? v0 : log1pf(__expf(v0));
                v1 = (v1 > 20.f) ? v1 : log1pf(__expf(v1));
                v2 = (v2 > 20.f) ? v2 : log1pf(__expf(v2));
                v3 = (v3 > 20.f) ? v3 : log1pf(__expf(v3));
            }
            *(float2*)&C[(size_t)m * ldc + n]       = make_float2(v0, v1);
            *(float2*)&C[(size_t)(m + 8) * ldc + n] = make_float2(v2, v3);
            if (EPI == 2 && n < DTRANK) {
                __half h0 = __float2half_rn(v0), h1 = __float2half_rn(v1);
                __half h2 = __float2half_rn(v2), h3 = __float2half_rn(v3);
                __half l0 = __float2half_rn(v0 - __half2float(h0));
                __half l1 = __float2half_rn(v1 - __half2float(h1));
                __half l2 = __float2half_rn(v2 - __half2float(h2));
                __half l3 = __float2half_rn(v3 - __half2float(h3));
                *(__half2*)&g_dth[(size_t)m * DTRANK + n] = __half2(h0, h1);
                *(__half2*)&g_dtl[(size_t)m * DTRANK + n] = __half2(l0, l1);
                *(__half2*)&g_dth[(size_t)(m + 8) * DTRANK + n] = __half2(h2, h3);
                *(__half2*)&g_dtl[(size_t)(m + 8) * DTRANK + n] = __half2(l2, l3);
            }
        }
    }
}

// ---------------------------------------------------------------------------
// One launch: all fp32 -> fp16 conversions (x and weights, hi only now).
// ---------------------------------------------------------------------------
#define N0 (BL*DMODEL)
#define N1 (D2*DMODEL)
#define N2 (DBCW*DINNER)
#define N3 (DINNER*DTRANK)
#define N4 (DMODEL*DINNER)
#define NT5 (N0+N1+N2+N3+N4)

__global__ __launch_bounds__(256)
void cvt_split5(const float* __restrict__ s0, const float* __restrict__ s1,
                const float* __restrict__ s2, const float* __restrict__ s3,
                const float* __restrict__ s4)
{
    int idx = blockIdx.x * 256 + threadIdx.x;
    if (idx >= NT5) return;
    const float* src; __half* hi; int off;
    if      (idx < N0)          { src = s0; hi = g_xh;    off = idx; }
    else if (idx < N0+N1)       { src = s1; hi = g_winh;  off = idx - N0; }
    else if (idx < N0+N1+N2)    { src = s2; hi = g_wxh;   off = idx - N0-N1; }
    else if (idx < N0+N1+N2+N3) { src = s3; hi = g_wdth;  off = idx - N0-N1-N2; }
    else                        { src = s4; hi = g_wouth; off = idx - N0-N1-N2-N3; }
    hi[off] = __float2half_rn(src[off]);
}

// ---------------------------------------------------------------------------
// Causal depthwise conv (k=4) + bias + SiLU; emits fp32 xc AND split fp16 xc
// ---------------------------------------------------------------------------
__global__ __launch_bounds__(256)
void conv_silu_kernel(const float* __restrict__ conv_w, const float* __restrict__ conv_b)
{
    const size_t idx = (size_t)blockIdx.x * 256 + threadIdx.x;
    if (idx >= (size_t)BL * DINNER) return;
    const int d  = (int)(idx % DINNER);
    const size_t bl = idx / DINNER;
    const int l  = (int)(bl % LENGTH);
    const size_t brow = (bl - l) * (size_t)D2;

    float acc = conv_b[d];
    const float w0 = conv_w[d*4+0], w1 = conv_w[d*4+1];
    const float w2 = conv_w[d*4+2], w3 = conv_w[d*4+3];
    const float* base = g_xz + brow + d;
    if (l >= 3) acc += w0 * base[(size_t)(l-3)*D2];
    if (l >= 2) acc += w1 * base[(size_t)(l-2)*D2];
    if (l >= 1) acc += w2 * base[(size_t)(l-1)*D2];
    acc += w3 * base[(size_t)l*D2];

    float s = acc / (1.f + __expf(-acc));
    g_xc[idx] = s;
    __half h = __float2half_rn(s);
    g_xch[idx] = h;
    g_xcl[idx] = __float2half_rn(s - __half2float(h));
}

// ---------------------------------------------------------------------------
// Selective scan v2: windowed cp.async staging (validated in R11).
// Emits single-fp16 y (GEMM4 is now 1-pass).
// ---------------------------------------------------------------------------
#define SW 16     // window timesteps
__global__ __launch_bounds__(128)
void scan_kernel(const float* __restrict__ A_raw, const float* __restrict__ Dvec)
{
    __shared__ __align__(16) float s_d [2][SW][16];
    __shared__ __align__(16) float s_x [2][SW][16];
    __shared__ __align__(16) float s_z [2][SW][16];
    __shared__ __align__(16) float s_bc[2][SW][32];

    const int tid = threadIdx.x;
    const int sub = tid & 7;
    const int ch  = tid >> 3;
    const int blk = blockIdx.x;
    const int b   = blk >> 7;
    const int c0  = (blk & 127) << 4;
    const int c   = c0 + ch;

    const float a0 = -__expf(A_raw[(2*sub+0)*DINNER + c]);
    const float a1 = -__expf(A_raw[(2*sub+1)*DINNER + c]);
    const float Dv = Dvec[c];

    const float* dbase  = g_delta + (size_t)b*LENGTH*DINNER + c0;
    const float* xbase  = g_xc    + (size_t)b*LENGTH*DINNER + c0;
    const float* zbase  = g_xz    + (size_t)b*LENGTH*D2 + DINNER + c0;
    const float* bcbase = g_dbc   + (size_t)b*LENGTH*DBCW + DTRANK;
    __half* yhp = g_yh + (size_t)b*LENGTH*DINNER + c;

    auto ld_win = [&](int s, int t0) {
        const int ttA = tid >> 2, qA = (tid & 3) * 4;
        if (tid < 64) {
            CP16(s2u(&s_d[s][ttA][qA]), dbase + (size_t)(t0 + ttA)*DINNER + qA);
            CP16(s2u(&s_z[s][ttA][qA]), zbase + (size_t)(t0 + ttA)*D2 + qA);
        } else {
            const int tt = (tid - 64) >> 2, q = ((tid - 64) & 3) * 4;
            CP16(s2u(&s_x[s][tt][q]), xbase + (size_t)(t0 + tt)*DINNER + q);
        }
        const int ttB = tid >> 3, qB = (tid & 7) * 4;
        CP16(s2u(&s_bc[s][ttB][qB]), bcbase + (size_t)(t0 + ttB)*DBCW + qB);
    };

    float h0 = 0.f, h1 = 0.f;
    const int NW = LENGTH / SW;

    ld_win(0, 0);    CP_COMMIT();
    ld_win(1, SW);   CP_COMMIT();

    for (int w = 0; w < NW; ++w) {
        CP_WAIT1();
        __syncthreads();
        const int buf = w & 1;
        const int t0  = w * SW;

#pragma unroll
        for (int tt = 0; tt < SW; ++tt) {
            const float d  = s_d[buf][tt][ch];
            const float xv = s_x[buf][tt][ch];
            const float2 Bv = *(const float2*)&s_bc[buf][tt][2*sub];
            const float2 Cv = *(const float2*)&s_bc[buf][tt][16 + 2*sub];
            const float dx = d * xv;

            h0 = fmaf(__expf(d * a0), h0, Bv.x * dx);
            h1 = fmaf(__expf(d * a1), h1, Bv.y * dx);

            float acc = Cv.x * h0 + Cv.y * h1;
            acc += __shfl_xor_sync(0xffffffffu, acc, 1);
            acc += __shfl_xor_sync(0xffffffffu, acc, 2);
            acc += __shfl_xor_sync(0xffffffffu, acc, 4);

            if (sub == 0) {
                const float z = s_z[buf][tt][ch];
                float y = (acc + Dv * xv) * (z / (1.f + __expf(-z)));
                yhp[(size_t)(t0 + tt) * DINNER] = __float2half_rn(y);
            }
        }

        __syncthreads();
        if (w + 2 < NW) ld_win(buf, (w + 2) * SW);
        CP_COMMIT();
    }
}

// ---------------------------------------------------------------------------
extern "C" void kernel_launch(void* const* d_in, const int* in_sizes, int n_in,
                              void* d_out, int out_size)
{
    const float* x      = (const float*)d_in[0];
    const float* W_in   = (const float*)d_in[1];
    const float* conv_w = (const float*)d_in[2];
    const float* conv_b = (const float*)d_in[3];
    const float* W_x    = (const float*)d_in[4];
    const float* W_dt   = (const float*)d_in[5];
    const float* b_dt   = (const float*)d_in[6];
    const float* A_raw  = (const float*)d_in[7];
    const float* Dvec   = (const float*)d_in[8];
    const float* W_out  = (const float*)d_in[9];
    float* out = (float*)d_out;

    float *p_xz, *p_dbc, *p_delta;
    __half *p_xh,*p_winh,*p_xch,*p_xcl,*p_wxh;
    __half *p_dth,*p_dtl,*p_wdth,*p_yh,*p_wouth;
    cudaGetSymbolAddress((void**)&p_xz,    g_xz);
    cudaGetSymbolAddress((void**)&p_dbc,   g_dbc);
    cudaGetSymbolAddress((void**)&p_delta, g_delta);
    cudaGetSymbolAddress((void**)&p_xh,    g_xh);
    cudaGetSymbolAddress((void**)&p_winh,  g_winh);
    cudaGetSymbolAddress((void**)&p_xch,   g_xch);
    cudaGetSymbolAddress((void**)&p_xcl,   g_xcl);
    cudaGetSymbolAddress((void**)&p_wxh,   g_wxh);
    cudaGetSymbolAddress((void**)&p_dth,   g_dth);
    cudaGetSymbolAddress((void**)&p_dtl,   g_dtl);
    cudaGetSymbolAddress((void**)&p_wdth,  g_wdth);
    cudaGetSymbolAddress((void**)&p_yh,    g_yh);
    cudaGetSymbolAddress((void**)&p_wouth, g_wouth);

    const int SMEM_1P128 = 3 * (1*128*80 + 128*80);   // 61440 (PASSES=1, MTILE=128)
    const int SMEM_2P64  = 3 * (2*64*80  + 128*80);   // 61440 (PASSES=2, MTILE=64)
    const int SMEM_2P128 = 3 * (2*128*80 + 128*80);   // 92160 (PASSES=2, MTILE=128)
    cudaFuncSetAttribute(tgemm<128,1,0,false>, cudaFuncAttributeMaxDynamicSharedMemorySize, SMEM_1P128);
    cudaFuncSetAttribute(tgemm< 64,2,2,true >, cudaFuncAttributeMaxDynamicSharedMemorySize, SMEM_2P64);
    cudaFuncSetAttribute(tgemm<128,2,1,false>, cudaFuncAttributeMaxDynamicSharedMemorySize, SMEM_2P128);

    // 0) all conversions in one launch
    cvt_split5<<<(NT5 + 255)/256, 256>>>(x, W_in, W_x, W_dt, W_out);

    // 1) xz = x @ W_in^T   (8192 x 4096, K=1024), 1-pass fp16
    tgemm<128,1,0,false><<<dim3(D2/128, BL/128), 256, SMEM_1P128>>>(
        p_xh, nullptr, DMODEL, p_winh, DMODEL, p_xz, D2, D2, DMODEL, nullptr);

    // 2) conv + silu (emits fp32 + split fp16 xc)
    conv_silu_kernel<<<(unsigned)(((size_t)BL*DINNER + 255)/256), 256>>>(conv_w, conv_b);

    // 3) dbc = xc @ W_x^T  (8192 x 96, K=2048), 2-pass, fused dt split
    tgemm<64,2,2,true><<<dim3(1, BL/64), 256, SMEM_2P64>>>(
        p_xch, p_xcl, DINNER, p_wxh, DINNER, p_dbc, DBCW, DBCW, DINNER, nullptr);

    // 4) delta = softplus(dt @ W_dt^T + b_dt)  (8192 x 2048, K=64), 2-pass
    tgemm<128,2,1,false><<<dim3(DINNER/128, BL/128), 256, SMEM_2P128>>>(
        p_dth, p_dtl, DTRANK, p_wdth, DTRANK, p_delta, DINNER, DINNER, DTRANK, b_dt);

    // 5) selective scan (windowed cp.async) -> single fp16 y
    scan_kernel<<<BATCH*128, 128>>>(A_raw, Dvec);

    // 6) out = y @ W_out^T (8192 x 1024, K=2048), 1-pass fp16
    tgemm<128,1,0,false><<<dim3(DMODEL/128, BL/128), 256, SMEM_1P128>>>(
        p_yh, nullptr, DINNER, p_wouth, DINNER, out, DMODEL, DMODEL, DINNER, nullptr);
}

// round 15
// speedup vs baseline: 5.7202x; 1.0292x over previous
#include <cuda_runtime.h>
#include <cuda_fp16.h>
#include <cstdint>

// Problem dims (fixed)
#define BATCH   4
#define LENGTH  2048
#define DMODEL  1024
#define DINNER  2048
#define DSTATE  16
#define DTRANK  64
#define BL      (BATCH*LENGTH)        // 8192
#define D2      (2*DINNER)            // 4096
#define DBCW    (DTRANK + 2*DSTATE)   // 96

// ------------------- static scratch (no cudaMalloc allowed) -------------------
__device__ float g_xz[(size_t)BL * D2];
__device__ float g_xc[(size_t)BL * DINNER];
__device__ float g_dbc[(size_t)BL * DBCW];
__device__ float g_delta[(size_t)BL * DINNER];

__device__ __half g_xh  [(size_t)BL*DMODEL];
__device__ __half g_winh[(size_t)D2*DMODEL];
__device__ __half g_xch [(size_t)BL*DINNER],   g_xcl [(size_t)BL*DINNER];
__device__ __half g_wxh [(size_t)DBCW*DINNER];
__device__ __half g_dth [(size_t)BL*DTRANK],   g_dtl [(size_t)BL*DTRANK];
__device__ __half g_wdth[(size_t)DINNER*DTRANK];
__device__ __half g_yh  [(size_t)BL*DINNER];
__device__ __half g_wouth[(size_t)DMODEL*DINNER];

// ------------------------------ PTX helpers ------------------------------
__device__ __forceinline__ uint32_t s2u(const void* p) {
    uint32_t a;
    asm("{ .reg .u64 t; cvta.to.shared.u64 t, %1; cvt.u32.u64 %0, t; }" : "=r"(a) : "l"(p));
    return a;
}
#define CP16(d, g) \
    asm volatile("cp.async.cg.shared.global [%0], [%1], 16;" :: "r"(d), "l"(g))
#define CP16Z(d, g, v) \
    asm volatile("cp.async.cg.shared.global [%0], [%1], 16, %2;" :: "r"(d), "l"(g), "r"(v))
#define CP_COMMIT() asm volatile("cp.async.commit_group;" ::: "memory")
#define CP_WAIT1()  asm volatile("cp.async.wait_group 1;" ::: "memory")

#define LDSM4(r, a) \
    asm volatile("ldmatrix.sync.aligned.m8n8.x4.shared.b16 {%0,%1,%2,%3}, [%4];" \
        : "=r"((r)[0]), "=r"((r)[1]), "=r"((r)[2]), "=r"((r)[3]) : "r"(a))

#define MMA16816(c, a, b0, b1) \
    asm volatile("mma.sync.aligned.m16n8k16.row.col.f32.f16.f16.f32 " \
        "{%0,%1,%2,%3}, {%4,%5,%6,%7}, {%8,%9}, {%0,%1,%2,%3};" \
        : "+f"((c)[0]), "+f"((c)[1]), "+f"((c)[2]), "+f"((c)[3]) \
        : "r"((a)[0]), "r"((a)[1]), "r"((a)[2]), "r"((a)[3]), "r"(b0), "r"(b1))

// ---------------------------------------------------------------------------
// Split-fp16 warp-MMA GEMM: C[m][n] = sum_k A[m][k]*B[n][k] (fp32 out)
// PASSES=2: A split (Ah+Al)·Bh.  PASSES=1: single Ah·Bh.
// CTA tile MTILE x 128, BK=64 (144B-padded rows, conflict-free ldmatrix),
// 256 threads (2x4 warps), 3-buffer cp.async pipeline with wait_group 1 and
// ONE __syncthreads per K-chunk, 2 CTAs/SM.
// EPI: 0 plain, 1 softplus(v+bias[n]), 2 plain + fused fp16 dt-split (n<64).
// GUARD: bounds-check B rows / C cols against Nt.
// NOTE: kernels with K<=64 (nit==1) only touch stage 0 — launch them with
// dynamic smem = 1*STG.
// ---------------------------------------------------------------------------
#define ROWB 144u    // 64 fp16 = 128B data + 16B pad

template<int MTILE, int PASSES, int EPI, bool GUARD>
__global__ __launch_bounds__(256, 2)
void tgemm(const __half* __restrict__ Ah, const __half* __restrict__ Al, int lda,
           const __half* __restrict__ Bh, int ldb,
           float* __restrict__ C, int ldc, int Nt, int K,
           const float* __restrict__ bias)
{
    constexpr uint32_t OFF_AL = (uint32_t)MTILE * ROWB;                 // if PASSES==2
    constexpr uint32_t OFF_B  = (uint32_t)PASSES * (uint32_t)MTILE * ROWB;
    constexpr uint32_t STG    = OFF_B + 128u * ROWB;
    constexpr int MI = MTILE / 32;

    extern __shared__ char smem[];
    const uint32_t sb = s2u(smem);

    const int tid = threadIdx.x;
    const int lid = tid & 31;
    const int wid = tid >> 5;
    const int wm0 = (wid & 1) * (MTILE / 2);
    const int wn0 = (wid >> 1) * 32;

    const int bm = blockIdx.y * MTILE;
    const int bn = blockIdx.x * 128;

    float acc[MI][4][4];
#pragma unroll
    for (int i = 0; i < MI; i++)
#pragma unroll
        for (int j = 0; j < 4; j++)
#pragma unroll
            for (int k = 0; k < 4; k++) acc[i][j][k] = 0.f;

    auto ld_stage = [&](int s, int kc) {
        const uint32_t base = sb + (uint32_t)s * STG;
        const __half* pAh = Ah + (size_t)bm * lda + kc;
        const __half* pAl = (PASSES == 2) ? (Al + (size_t)bm * lda + kc) : pAh;
        const __half* pBh = Bh + (size_t)bn * ldb + kc;
        // A: MTILE rows x 128B = MTILE*8 16B-chunks
#pragma unroll
        for (int i = 0; i < (MTILE * 8) / 256; ++i) {
            const int c   = tid + i * 256;
            const int row = c >> 3;
            const int ch  = (c & 7) * 16;
            const uint32_t o = (uint32_t)row * ROWB + (uint32_t)ch;
            CP16(base + o, (const char*)(pAh + (size_t)row * lda) + ch);
            if (PASSES == 2)
                CP16(base + OFF_AL + o, (const char*)(pAl + (size_t)row * lda) + ch);
        }
        // B: 128 rows x 128B = 1024 chunks
#pragma unroll
        for (int i = 0; i < 4; ++i) {
            const int c   = tid + i * 256;
            const int row = c >> 3;
            const int ch  = (c & 7) * 16;
            const uint32_t o = (uint32_t)row * ROWB + (uint32_t)ch;
            if (!GUARD) {
                CP16(base + OFF_B + o, (const char*)(pBh + (size_t)row * ldb) + ch);
            } else {
                const uint32_t v = ((bn + row) < Nt) ? 16u : 0u;
                CP16Z(base + OFF_B + o, (const char*)(pBh + (size_t)row * ldb) + ch, v);
            }
        }
    };

    const uint32_t arow  = (uint32_t)(wm0 + (lid & 15));
    const uint32_t akoff = (uint32_t)((lid >> 4) << 3);
    const uint32_t brow  = (uint32_t)(wn0 + ((lid >> 4) << 3) + (lid & 7));
    const uint32_t bkoff = (uint32_t)(((lid >> 3) & 1) << 3);

    auto compute = [&](int s) {
        const uint32_t aB = sb + (uint32_t)s * STG;
        const uint32_t bB = aB + OFF_B;
#pragma unroll
        for (int kk = 0; kk < 4; ++kk) {              // 4 x k16 per BK=64
            uint32_t bh[2][4];
#pragma unroll
            for (int bi = 0; bi < 2; bi++) {
                const uint32_t bd = bB + (brow + bi*16) * ROWB + (bkoff + kk*16) * 2u;
                LDSM4(bh[bi], bd);
            }
#pragma unroll
            for (int mi = 0; mi < MI; mi++) {
                uint32_t ah[4], al[4];
                const uint32_t ad = aB + (arow + mi*16) * ROWB + (akoff + kk*16) * 2u;
                LDSM4(ah, ad);
                if (PASSES == 2) LDSM4(al, ad + OFF_AL);
#pragma unroll
                for (int nt = 0; nt < 4; nt++) {
                    const uint32_t b0 = bh[nt>>1][(nt&1)*2], b1 = bh[nt>>1][(nt&1)*2+1];
                    MMA16816(acc[mi][nt], ah, b0, b1);
                    if (PASSES == 2) MMA16816(acc[mi][nt], al, b0, b1);
                }
            }
        }
    };

    const int nit = K >> 6;                 // BK=64 chunks (>=1)
    ld_stage(0, 0);
    CP_COMMIT();
    if (nit > 1) ld_stage(1, 64);
    CP_COMMIT();                            // (possibly empty group)
    for (int it = 0; it < nit; ++it) {
        CP_WAIT1();
        __syncthreads();
        if (it + 2 < nit) ld_stage((it + 2) % 3, (it + 2) * 64);
        CP_COMMIT();
        compute(it % 3);
    }

    const int g  = lid >> 2;
    const int tg = lid & 3;
#pragma unroll
    for (int mi = 0; mi < MI; mi++) {
#pragma unroll
        for (int nt = 0; nt < 4; nt++) {
            const int m = bm + wm0 + mi * 16 + g;
            const int n = bn + wn0 + nt * 8 + 2 * tg;
            if (GUARD && n >= Nt) continue;
            float v0 = acc[mi][nt][0], v1 = acc[mi][nt][1];
            float v2 = acc[mi][nt][2], v3 = acc[mi][nt][3];
            if (EPI == 1) {
                const float b0 = bias[n], b1 = bias[n + 1];
                v0 += b0; v1 += b1; v2 += b0; v3 += b1;
                v0 = (v0 > 20.f) ? v0 : log1pf(__expf(v0));
                v1 = (v1 > 20.f) ? v1 : log1pf(__expf(v1));
                v2 = (v2 > 20.f) ? v2 : log1pf(__expf(v2));
                v3 = (v3 > 20.f) ? v3 : log1pf(__expf(v3));
            }
            *(float2*)&C[(size_t)m * ldc + n]       = make_float2(v0, v1);
            *(float2*)&C[(size_t)(m + 8) * ldc + n] = make_float2(v2, v3);
            if (EPI == 2 && n < DTRANK) {
                __half h0 = __float2half_rn(v0), h1 = __float2half_rn(v1);
                __half h2 = __float2half_rn(v2), h3 = __float2half_rn(v3);
                __half l0 = __float2half_rn(v0 - __half2float(h0));
                __half l1 = __float2half_rn(v1 - __half2float(h1));
                __half l2 = __float2half_rn(v2 - __half2float(h2));
                __half l3 = __float2half_rn(v3 - __half2float(h3));
                *(__half2*)&g_dth[(size_t)m * DTRANK + n] = __half2(h0, h1);
                *(__half2*)&g_dtl[(size_t)m * DTRANK + n] = __half2(l0, l1);
                *(__half2*)&g_dth[(size_t)(m + 8) * DTRANK + n] = __half2(h2, h3);
                *(__half2*)&g_dtl[(size_t)(m + 8) * DTRANK + n] = __half2(l2, l3);
            }
        }
    }
}

// ---------------------------------------------------------------------------
// One launch: all fp32 -> fp16 conversions.
// ---------------------------------------------------------------------------
#define N0 (BL*DMODEL)
#define N1 (D2*DMODEL)
#define N2 (DBCW*DINNER)
#define N3 (DINNER*DTRANK)
#define N4 (DMODEL*DINNER)
#define NT5 (N0+N1+N2+N3+N4)

__global__ __launch_bounds__(256)
void cvt_split5(const float* __restrict__ s0, const float* __restrict__ s1,
                const float* __restrict__ s2, const float* __restrict__ s3,
                const float* __restrict__ s4)
{
    int idx = blockIdx.x * 256 + threadIdx.x;
    if (idx >= NT5) return;
    const float* src; __half* hi; int off;
    if      (idx < N0)          { src = s0; hi = g_xh;    off = idx; }
    else if (idx < N0+N1)       { src = s1; hi = g_winh;  off = idx - N0; }
    else if (idx < N0+N1+N2)    { src = s2; hi = g_wxh;   off = idx - N0-N1; }
    else if (idx < N0+N1+N2+N3) { src = s3; hi = g_wdth;  off = idx - N0-N1-N2; }
    else                        { src = s4; hi = g_wouth; off = idx - N0-N1-N2-N3; }
    hi[off] = __float2half_rn(src[off]);
}

// ---------------------------------------------------------------------------
// Causal depthwise conv (k=4) + bias + SiLU; emits fp32 xc AND split fp16 xc
// ---------------------------------------------------------------------------
__global__ __launch_bounds__(256)
void conv_silu_kernel(const float* __restrict__ conv_w, const float* __restrict__ conv_b)
{
    const size_t idx = (size_t)blockIdx.x * 256 + threadIdx.x;
    if (idx >= (size_t)BL * DINNER) return;
    const int d  = (int)(idx % DINNER);
    const size_t bl = idx / DINNER;
    const int l  = (int)(bl % LENGTH);
    const size_t brow = (bl - l) * (size_t)D2;

    float acc = conv_b[d];
    const float w0 = conv_w[d*4+0], w1 = conv_w[d*4+1];
    const float w2 = conv_w[d*4+2], w3 = conv_w[d*4+3];
    const float* base = g_xz + brow + d;
    if (l >= 3) acc += w0 * base[(size_t)(l-3)*D2];
    if (l >= 2) acc += w1 * base[(size_t)(l-2)*D2];
    if (l >= 1) acc += w2 * base[(size_t)(l-1)*D2];
    acc += w3 * base[(size_t)l*D2];

    float s = acc / (1.f + __expf(-acc));
    g_xc[idx] = s;
    __half h = __float2half_rn(s);
    g_xch[idx] = h;
    g_xcl[idx] = __float2half_rn(s - __half2float(h));
}

// ---------------------------------------------------------------------------
// Selective scan: windowed cp.async staging (validated in R11/R13).
// ---------------------------------------------------------------------------
#define SW 16
__global__ __launch_bounds__(128)
void scan_kernel(const float* __restrict__ A_raw, const float* __restrict__ Dvec)
{
    __shared__ __align__(16) float s_d [2][SW][16];
    __shared__ __align__(16) float s_x [2][SW][16];
    __shared__ __align__(16) float s_z [2][SW][16];
    __shared__ __align__(16) float s_bc[2][SW][32];

    const int tid = threadIdx.x;
    const int sub = tid & 7;
    const int ch  = tid >> 3;
    const int blk = blockIdx.x;
    const int b   = blk >> 7;
    const int c0  = (blk & 127) << 4;
    const int c   = c0 + ch;

    const float a0 = -__expf(A_raw[(2*sub+0)*DINNER + c]);
    const float a1 = -__expf(A_raw[(2*sub+1)*DINNER + c]);
    const float Dv = Dvec[c];

    const float* dbase  = g_delta + (size_t)b*LENGTH*DINNER + c0;
    const float* xbase  = g_xc    + (size_t)b*LENGTH*DINNER + c0;
    const float* zbase  = g_xz    + (size_t)b*LENGTH*D2 + DINNER + c0;
    const float* bcbase = g_dbc   + (size_t)b*LENGTH*DBCW + DTRANK;
    __half* yhp = g_yh + (size_t)b*LENGTH*DINNER + c;

    auto ld_win = [&](int s, int t0) {
        const int ttA = tid >> 2, qA = (tid & 3) * 4;
        if (tid < 64) {
            CP16(s2u(&s_d[s][ttA][qA]), dbase + (size_t)(t0 + ttA)*DINNER + qA);
            CP16(s2u(&s_z[s][ttA][qA]), zbase + (size_t)(t0 + ttA)*D2 + qA);
        } else {
            const int tt = (tid - 64) >> 2, q = ((tid - 64) & 3) * 4;
            CP16(s2u(&s_x[s][tt][q]), xbase + (size_t)(t0 + tt)*DINNER + q);
        }
        const int ttB = tid >> 3, qB = (tid & 7) * 4;
        CP16(s2u(&s_bc[s][ttB][qB]), bcbase + (size_t)(t0 + ttB)*DBCW + qB);
    };

    float h0 = 0.f, h1 = 0.f;
    const int NW = LENGTH / SW;

    ld_win(0, 0);    CP_COMMIT();
    ld_win(1, SW);   CP_COMMIT();

    for (int w = 0; w < NW; ++w) {
        CP_WAIT1();
        __syncthreads();
        const int buf = w & 1;
        const int t0  = w * SW;

#pragma unroll
        for (int tt = 0; tt < SW; ++tt) {
            const float d  = s_d[buf][tt][ch];
            const float xv = s_x[buf][tt][ch];
            const float2 Bv = *(const float2*)&s_bc[buf][tt][2*sub];
            const float2 Cv = *(const float2*)&s_bc[buf][tt][16 + 2*sub];
            const float dx = d * xv;

            h0 = fmaf(__expf(d * a0), h0, Bv.x * dx);
            h1 = fmaf(__expf(d * a1), h1, Bv.y * dx);

            float acc = Cv.x * h0 + Cv.y * h1;
            acc += __shfl_xor_sync(0xffffffffu, acc, 1);
            acc += __shfl_xor_sync(0xffffffffu, acc, 2);
            acc += __shfl_xor_sync(0xffffffffu, acc, 4);

            if (sub == 0) {
                const float z = s_z[buf][tt][ch];
                float y = (acc + Dv * xv) * (z / (1.f + __expf(-z)));
                yhp[(size_t)(t0 + tt) * DINNER] = __float2half_rn(y);
            }
        }

        __syncthreads();
        if (w + 2 < NW) ld_win(buf, (w + 2) * SW);
        CP_COMMIT();
    }
}

// ---------------------------------------------------------------------------
extern "C" void kernel_launch(void* const* d_in, const int* in_sizes, int n_in,
                              void* d_out, int out_size)
{
    const float* x      = (const float*)d_in[0];
    const float* W_in   = (const float*)d_in[1];
    const float* conv_w = (const float*)d_in[2];
    const float* conv_b = (const float*)d_in[3];
    const float* W_x    = (const float*)d_in[4];
    const float* W_dt   = (const float*)d_in[5];
    const float* b_dt   = (const float*)d_in[6];
    const float* A_raw  = (const float*)d_in[7];
    const float* Dvec   = (const float*)d_in[8];
    const float* W_out  = (const float*)d_in[9];
    float* out = (float*)d_out;

    float *p_xz, *p_dbc, *p_delta;
    __half *p_xh,*p_winh,*p_xch,*p_xcl,*p_wxh;
    __half *p_dth,*p_dtl,*p_wdth,*p_yh,*p_wouth;
    cudaGetSymbolAddress((void**)&p_xz,    g_xz);
    cudaGetSymbolAddress((void**)&p_dbc,   g_dbc);
    cudaGetSymbolAddress((void**)&p_delta, g_delta);
    cudaGetSymbolAddress((void**)&p_xh,    g_xh);
    cudaGetSymbolAddress((void**)&p_winh,  g_winh);
    cudaGetSymbolAddress((void**)&p_xch,   g_xch);
    cudaGetSymbolAddress((void**)&p_xcl,   g_xcl);
    cudaGetSymbolAddress((void**)&p_wxh,   g_wxh);
    cudaGetSymbolAddress((void**)&p_dth,   g_dth);
    cudaGetSymbolAddress((void**)&p_dtl,   g_dtl);
    cudaGetSymbolAddress((void**)&p_wdth,  g_wdth);
    cudaGetSymbolAddress((void**)&p_yh,    g_yh);
    cudaGetSymbolAddress((void**)&p_wouth, g_wouth);

    // stage bytes: (PASSES*MTILE + 128) * 144
    const int STG_1P128 = (128 + 128) * 144;        // 36864
    const int STG_2P64  = (128 + 128) * 144;        // 36864
    const int STG_2P128 = (256 + 128) * 144;        // 55296
    const int SMEM_1P128 = 3 * STG_1P128;           // 110592 (2 CTAs/SM: 221184)
    const int SMEM_2P64  = 3 * STG_2P64;            // 110592
    const int SMEM_2P128 = 1 * STG_2P128;           // 55296  (K=64 -> only stage 0)
    cudaFuncSetAttribute(tgemm<128,1,0,false>, cudaFuncAttributeMaxDynamicSharedMemorySize, SMEM_1P128);
    cudaFuncSetAttribute(tgemm< 64,2,2,true >, cudaFuncAttributeMaxDynamicSharedMemorySize, SMEM_2P64);
    cudaFuncSetAttribute(tgemm<128,2,1,false>, cudaFuncAttributeMaxDynamicSharedMemorySize, SMEM_2P128);

    // 0) all conversions in one launch
    cvt_split5<<<(NT5 + 255)/256, 256>>>(x, W_in, W_x, W_dt, W_out);

    // 1) xz = x @ W_in^T   (8192 x 4096, K=1024), 1-pass fp16, BK=64
    tgemm<128,1,0,false><<<dim3(D2/128, BL/128), 256, SMEM_1P128>>>(
        p_xh, nullptr, DMODEL, p_winh, DMODEL, p_xz, D2, D2, DMODEL, nullptr);

    // 2) conv + silu (emits fp32 + split fp16 xc)
    conv_silu_kernel<<<(unsigned)(((size_t)BL*DINNER + 255)/256), 256>>>(conv_w, conv_b);

    // 3) dbc = xc @ W_x^T  (8192 x 96, K=2048), 2-pass, fused dt split
    tgemm<64,2,2,true><<<dim3(1, BL/64), 256, SMEM_2P64>>>(
        p_xch, p_xcl, DINNER, p_wxh, DINNER, p_dbc, DBCW, DBCW, DINNER, nullptr);

    // 4) delta = softplus(dt @ W_dt^T + b_dt)  (8192 x 2048, K=64), 2-pass, 1 chunk
    tgemm<128,2,1,false><<<dim3(DINNER/128, BL/128), 256, SMEM_2P128>>>(
        p_dth, p_dtl, DTRANK, p_wdth, DTRANK, p_delta, DINNER, DINNER, DTRANK, b_dt);

    // 5) selective scan (windowed cp.async) -> single fp16 y
    scan_kernel<<<BATCH*128, 128>>>(A_raw, Dvec);

    // 6) out = y @ W_out^T (8192 x 1024, K=2048), 1-pass fp16, BK=64
    tgemm<128,1,0,false><<<dim3(DMODEL/128, BL/128), 256, SMEM_1P128>>>(
        p_yh, nullptr, DINNER, p_wouth, DINNER, out, DMODEL, DMODEL, DINNER, nullptr);
}